// round 6
// baseline (speedup 1.0000x reference)
#include <cuda_runtime.h>
#include <cuda_bf16.h>
#include <cstdint>

#define BATCH 4
#define SEQ 2048
#define DMODEL 1024
#define NHEADS 16
#define HDIM 64
#define MROWS (BATCH * SEQ)      // 8192

// Scratch (device globals; all matmul operands live as tf32 bit patterns)
__device__ uint32_t g_x [MROWS * DMODEL];               // x, tf32 bits
__device__ uint32_t g_wq[DMODEL * DMODEL];
__device__ uint32_t g_wk[DMODEL * DMODEL];
__device__ uint32_t g_wv[DMODEL * DMODEL];
__device__ uint32_t g_wo[DMODEL * DMODEL];
__device__ uint32_t g_q [BATCH * NHEADS * SEQ * HDIM];  // [B,H,S,Dh] tf32 bits
__device__ uint32_t g_k [BATCH * NHEADS * SEQ * HDIM];
__device__ uint32_t g_v [BATCH * NHEADS * SEQ * HDIM];
__device__ uint32_t g_ao[BATCH * SEQ * DMODEL];         // [B,S,D] tf32 bits

__device__ __forceinline__ uint32_t f2tf32(float x) {
    uint32_t r;
    asm("cvt.rna.tf32.f32 %0, %1;" : "=r"(r) : "f"(x));
    return r;
}
__device__ __forceinline__ void mma_tf32(float* c, const uint32_t* a, const uint32_t* b) {
    asm volatile(
        "mma.sync.aligned.m16n8k8.row.col.f32.tf32.tf32.f32 "
        "{%0,%1,%2,%3}, {%4,%5,%6,%7}, {%8,%9}, {%0,%1,%2,%3};"
        : "+f"(c[0]), "+f"(c[1]), "+f"(c[2]), "+f"(c[3])
        : "r"(a[0]), "r"(a[1]), "r"(a[2]), "r"(a[3]), "r"(b[0]), "r"(b[1]));
}
__device__ __forceinline__ uint32_t smem_u32(const void* p) {
    return (uint32_t)__cvta_generic_to_shared(p);
}
__device__ __forceinline__ void cp16(uint32_t dst, const void* src) {
    asm volatile("cp.async.cg.shared.global [%0], [%1], 16;" :: "r"(dst), "l"(src));
}
__device__ __forceinline__ void cp_commit() { asm volatile("cp.async.commit_group;"); }
template<int N> __device__ __forceinline__ void cp_wait() {
    asm volatile("cp.async.wait_group %0;" :: "n"(N));
}

// ---------------------------------------------------------------------------
// fp32 -> tf32-bits elementwise convert
// ---------------------------------------------------------------------------
__global__ __launch_bounds__(256) void cvt_tf32_kernel(
    const float4* __restrict__ in, uint4* __restrict__ out, int n4)
{
    const int i = blockIdx.x * blockDim.x + threadIdx.x;
    if (i < n4) {
        float4 v = in[i];
        uint4 o;
        o.x = f2tf32(v.x); o.y = f2tf32(v.y);
        o.z = f2tf32(v.z); o.w = f2tf32(v.w);
        out[i] = o;
    }
}

// ---------------------------------------------------------------------------
// Pipelined tf32 GEMM core (operands already tf32 bits, no cvt in loop).
// C = A[M,K] * B[N,K]^T, 128x128 block, BK=16, 4-stage cp.async.
// ---------------------------------------------------------------------------
#define GKS 20
#define GEMM_SMEM_U32 (2 * 4 * 128 * GKS)

struct GemmAcc { float a[4][4][4]; };

__device__ __forceinline__ void gemm_core(
    const uint32_t* __restrict__ A, const uint32_t* __restrict__ Bw,
    uint32_t* As, uint32_t* Bs, int bm, int bn, GemmAcc& G)
{
    const int tid  = threadIdx.x;
    const int warp = tid >> 5;
    const int lane = tid & 31;
    const int wm = warp >> 2;
    const int wn = warp & 3;
    const int r = lane >> 2;
    const int c = lane & 3;

    const int lch = tid & 3;
    const int lrw = tid >> 2;
    const uint32_t* Agl = A  + (bm + lrw) * DMODEL + lch * 4;
    const uint32_t* Bgl = Bw + (bn + lrw) * DMODEL + lch * 4;
    const uint32_t aB = smem_u32(As);
    const uint32_t bB = smem_u32(Bs);
    const uint32_t dOff = ((uint32_t)(lrw * GKS + lch * 4)) * 4u;
    const uint32_t rowHalf = 64u * GKS * 4u;

    auto issue = [&](int s) {
        const int buf = s & 3;
        const int k0 = s << 4;
        const uint32_t sb = (uint32_t)(buf * 128 * GKS) * 4u;
        cp16(aB + sb + dOff, Agl + k0);
        cp16(aB + sb + dOff + rowHalf, Agl + 64 * DMODEL + k0);
        cp16(bB + sb + dOff, Bgl + k0);
        cp16(bB + sb + dOff + rowHalf, Bgl + 64 * DMODEL + k0);
    };

    issue(0); cp_commit();
    issue(1); cp_commit();
    issue(2); cp_commit();

#pragma unroll
    for (int i = 0; i < 4; i++)
#pragma unroll
        for (int j = 0; j < 4; j++)
#pragma unroll
            for (int q = 0; q < 4; q++) G.a[i][j][q] = 0.0f;

    for (int t = 0; t < 64; t++) {
        cp_wait<2>();
        __syncthreads();
        if (t + 3 < 64) issue(t + 3);
        cp_commit();

        const uint32_t* Ab = As + (t & 3) * 128 * GKS;
        const uint32_t* Bb = Bs + (t & 3) * 128 * GKS;
#pragma unroll
        for (int ks = 0; ks < 16; ks += 8) {
            uint32_t af[4][4], bf[4][2];
#pragma unroll
            for (int mt = 0; mt < 4; mt++) {
                const int m = wm * 64 + mt * 16 + r;
                af[mt][0] = Ab[m * GKS + ks + c];
                af[mt][1] = Ab[(m + 8) * GKS + ks + c];
                af[mt][2] = Ab[m * GKS + ks + c + 4];
                af[mt][3] = Ab[(m + 8) * GKS + ks + c + 4];
            }
#pragma unroll
            for (int nt = 0; nt < 4; nt++) {
                const int n = wn * 32 + nt * 8 + r;
                bf[nt][0] = Bb[n * GKS + ks + c];
                bf[nt][1] = Bb[n * GKS + ks + c + 4];
            }
#pragma unroll
            for (int mt = 0; mt < 4; mt++)
#pragma unroll
                for (int nt = 0; nt < 4; nt++)
                    mma_tf32(G.a[mt][nt], af[mt], bf[nt]);
        }
    }
}

// Fused QKV projection: gridDim.z selects weight/output; scatter tf32 bits.
__global__ __launch_bounds__(256, 2) void gemm_qkv_kernel(
    const uint32_t* __restrict__ X,
    const uint32_t* __restrict__ Wq, const uint32_t* __restrict__ Wk,
    const uint32_t* __restrict__ Wv,
    uint32_t* __restrict__ Oq, uint32_t* __restrict__ Ok,
    uint32_t* __restrict__ Ov)
{
    extern __shared__ uint32_t gsm[];
    const uint32_t* W = (blockIdx.z == 0) ? Wq : (blockIdx.z == 1) ? Wk : Wv;
    uint32_t* C = (blockIdx.z == 0) ? Oq : (blockIdx.z == 1) ? Ok : Ov;

    const int bm = blockIdx.y << 7;
    const int bn = blockIdx.x << 7;
    GemmAcc G;
    gemm_core(X, W, gsm, gsm + 4 * 128 * GKS, bm, bn, G);

    const int lane = threadIdx.x & 31;
    const int warp = threadIdx.x >> 5;
    const int r = lane >> 2, c = lane & 3;
    const int wm = warp >> 2, wn = warp & 3;
#pragma unroll
    for (int mt = 0; mt < 4; mt++) {
        const int m0 = bm + wm * 64 + mt * 16 + r;
#pragma unroll
        for (int nt = 0; nt < 4; nt++) {
            const int n = bn + wn * 32 + nt * 8 + c * 2;
            const int h = n >> 6;
            const int dh = n & 63;
#pragma unroll
            for (int half = 0; half < 2; half++) {
                const int m = m0 + half * 8;
                const int b = m >> 11;
                const int s = m & (SEQ - 1);
                uint2 v = make_uint2(f2tf32(G.a[mt][nt][half * 2]),
                                     f2tf32(G.a[mt][nt][half * 2 + 1]));
                *(uint2*)&C[((b * NHEADS + h) * SEQ + s) * HDIM + dh] = v;
            }
        }
    }
}

// O projection: fp32 row-major output.
__global__ __launch_bounds__(256, 2) void gemm_o_kernel(
    const uint32_t* __restrict__ A, const uint32_t* __restrict__ W,
    float* __restrict__ C)
{
    extern __shared__ uint32_t gsm[];
    const int bm = blockIdx.y << 7;
    const int bn = blockIdx.x << 7;
    GemmAcc G;
    gemm_core(A, W, gsm, gsm + 4 * 128 * GKS, bm, bn, G);

    const int lane = threadIdx.x & 31;
    const int warp = threadIdx.x >> 5;
    const int r = lane >> 2, c = lane & 3;
    const int wm = warp >> 2, wn = warp & 3;
#pragma unroll
    for (int mt = 0; mt < 4; mt++) {
        const int m0 = bm + wm * 64 + mt * 16 + r;
#pragma unroll
        for (int nt = 0; nt < 4; nt++) {
            const int n = bn + wn * 32 + nt * 8 + c * 2;
#pragma unroll
            for (int half = 0; half < 2; half++) {
                const int m = m0 + half * 8;
                float2 v = make_float2(G.a[mt][nt][half * 2],
                                       G.a[mt][nt][half * 2 + 1]);
                *(float2*)&C[m * DMODEL + n] = v;
            }
        }
    }
}

// ---------------------------------------------------------------------------
// Pipelined tf32 flash attention (causal), operands are tf32 bits.
// 256 threads = 8 warps; q-tile 128, kv-tile 64, double-buffered cp.async.
// Base-2 softmax: Q pre-scaled by 0.125*log2(e).
// ---------------------------------------------------------------------------
#define AKS 68
#define AVS 72
#define APS 68
#define ATT_SMEM_U32 (2 * 64 * AKS + 2 * 64 * AVS + 128 * APS)
#define QSCALE (0.125f * 1.4426950408889634f)

__global__ __launch_bounds__(256, 2) void attn_pipe_kernel(
    const uint32_t* __restrict__ Q, const uint32_t* __restrict__ K,
    const uint32_t* __restrict__ V, uint32_t* __restrict__ O)
{
    extern __shared__ uint32_t smu[];
    uint32_t* Ks = smu;                              // [2][64][68]
    uint32_t* Vs = smu + 2 * 64 * AKS;               // [2][64][72]
    uint32_t* Pu = smu + 2 * 64 * AKS + 2 * 64 * AVS; // [128][68]

    const int tid  = threadIdx.x;
    const int warp = tid >> 5;
    const int lane = tid & 31;
    const int r = lane >> 2;
    const int c = lane & 3;

    const int bh = blockIdx.y;
    const int QT = gridDim.x - 1 - blockIdx.x;    // longest first
    const int q0 = QT << 7;
    const uint32_t* Qb = Q + bh * (SEQ * HDIM);
    const uint32_t* Kb = K + bh * (SEQ * HDIM);
    const uint32_t* Vb = V + bh * (SEQ * HDIM);

    // ---- stage Q tile (128x64 bits) into Pu ----
    {
        const int qrow = tid >> 1;
        const int qcol = (tid & 1) << 5;
#pragma unroll
        for (int cc = 0; cc < 32; cc += 4)
            *(uint4*)&Pu[qrow * APS + qcol + cc] =
                *(const uint4*)&Qb[(q0 + qrow) * HDIM + qcol + cc];
    }
    __syncthreads();

    const int qr = warp * 16 + r;
    uint32_t qf[8][4];
#pragma unroll
    for (int ks = 0; ks < 8; ks++) {
        const int d = ks * 8 + c;
        qf[ks][0] = f2tf32(QSCALE * __uint_as_float(Pu[qr * APS + d]));
        qf[ks][1] = f2tf32(QSCALE * __uint_as_float(Pu[(qr + 8) * APS + d]));
        qf[ks][2] = f2tf32(QSCALE * __uint_as_float(Pu[qr * APS + d + 4]));
        qf[ks][3] = f2tf32(QSCALE * __uint_as_float(Pu[(qr + 8) * APS + d + 4]));
    }

    // ---- KV loader (cp.async) ----
    const int ch  = tid & 15;
    const int lr0 = tid >> 4;
    const uint32_t ksB = smem_u32(Ks);
    const uint32_t vsB = smem_u32(Vs);

    auto issue_kv = [&](int t) {
        const int buf = t & 1;
        const int k0 = t << 6;
#pragma unroll
        for (int j = 0; j < 4; j++) {
            const int row = lr0 + 16 * j;
            cp16(ksB + ((buf * 64 + row) * AKS + ch * 4) * 4u,
                 Kb + (k0 + row) * HDIM + ch * 4);
            cp16(vsB + ((buf * 64 + row) * AVS + ch * 4) * 4u,
                 Vb + (k0 + row) * HDIM + ch * 4);
        }
    };

    issue_kv(0); cp_commit();

    float oacc[8][4];
#pragma unroll
    for (int nt = 0; nt < 8; nt++)
#pragma unroll
        for (int j = 0; j < 4; j++) oacc[nt][j] = 0.0f;
    float mrun[2] = {-1e30f, -1e30f};
    float lrun[2] = {0.0f, 0.0f};

    const int T = 2 * QT + 1;
    for (int t = 0; t <= T; t++) {
        cp_wait<0>();
        __syncthreads();
        if (t < T) issue_kv(t + 1);
        cp_commit();

        const uint32_t* Kt = Ks + (t & 1) * 64 * AKS;
        const uint32_t* Vt = Vs + (t & 1) * 64 * AVS;

        // ---- scores (log2-scaled) ----
        float sacc[8][4];
#pragma unroll
        for (int nt = 0; nt < 8; nt++)
#pragma unroll
            for (int j = 0; j < 4; j++) sacc[nt][j] = 0.0f;
#pragma unroll
        for (int ks = 0; ks < 8; ks++) {
#pragma unroll
            for (int nt = 0; nt < 8; nt++) {
                uint32_t kb[2];
                const int base = (nt * 8 + r) * AKS + ks * 8 + c;
                kb[0] = Kt[base];
                kb[1] = Kt[base + 4];
                mma_tf32(sacc[nt], qf[ks], kb);
            }
        }

        // ---- causal mask (diagonal region only) ----
        if (t >= 2 * QT) {
            const int kbase = t << 6;
#pragma unroll
            for (int nt = 0; nt < 8; nt++)
#pragma unroll
                for (int j = 0; j < 4; j++) {
                    const int kg = kbase + nt * 8 + 2 * c + (j & 1);
                    const int qg = q0 + warp * 16 + r + (j >> 1) * 8;
                    if (kg > qg) sacc[nt][j] = -1e30f;
                }
        }

        // ---- online softmax (base 2) ----
#pragma unroll
        for (int hh = 0; hh < 2; hh++) {
            float tm = -1e30f;
#pragma unroll
            for (int nt = 0; nt < 8; nt++)
                tm = fmaxf(tm, fmaxf(sacc[nt][2 * hh], sacc[nt][2 * hh + 1]));
            tm = fmaxf(tm, __shfl_xor_sync(0xffffffffu, tm, 1));
            tm = fmaxf(tm, __shfl_xor_sync(0xffffffffu, tm, 2));
            const float mnew  = fmaxf(mrun[hh], tm);
            const float alpha = exp2f(mrun[hh] - mnew);
            float ls = 0.0f;
            const int prow = (warp * 16 + r + hh * 8) * APS;
#pragma unroll
            for (int nt = 0; nt < 8; nt++) {
                const float p0 = exp2f(sacc[nt][2 * hh] - mnew);
                const float p1 = exp2f(sacc[nt][2 * hh + 1] - mnew);
                ls += p0 + p1;
                uint2 pv = make_uint2(f2tf32(p0), f2tf32(p1));
                *(uint2*)&Pu[prow + nt * 8 + 2 * c] = pv;
            }
            ls += __shfl_xor_sync(0xffffffffu, ls, 1);
            ls += __shfl_xor_sync(0xffffffffu, ls, 2);
            lrun[hh] = lrun[hh] * alpha + ls;
            mrun[hh] = mnew;
#pragma unroll
            for (int nt = 0; nt < 8; nt++) {
                oacc[nt][2 * hh]     *= alpha;
                oacc[nt][2 * hh + 1] *= alpha;
            }
        }
        __syncwarp();   // P region is warp-local: order STS before LDS

        // ---- O += P V ----
#pragma unroll
        for (int ks = 0; ks < 8; ks++) {
            uint32_t pf[4];
            const int d = ks * 8 + c;
            pf[0] = Pu[qr * APS + d];
            pf[1] = Pu[(qr + 8) * APS + d];
            pf[2] = Pu[qr * APS + d + 4];
            pf[3] = Pu[(qr + 8) * APS + d + 4];
#pragma unroll
            for (int nt = 0; nt < 8; nt++) {
                uint32_t vb[2];
                vb[0] = Vt[(ks * 8 + c) * AVS + nt * 8 + r];
                vb[1] = Vt[(ks * 8 + c + 4) * AVS + nt * 8 + r];
                mma_tf32(oacc[nt], pf, vb);
            }
        }
    }

    // ---- epilogue: normalize, write tf32 bits to [B,S,D] ----
    const float rinv0 = 1.0f / lrun[0];
    const float rinv1 = 1.0f / lrun[1];
    const int b = bh >> 4, h = bh & 15;
    const int row0 = q0 + qr;
#pragma unroll
    for (int nt = 0; nt < 8; nt++) {
        const int dh = nt * 8 + 2 * c;
        uint2 v0 = make_uint2(f2tf32(oacc[nt][0] * rinv0), f2tf32(oacc[nt][1] * rinv0));
        uint2 v1 = make_uint2(f2tf32(oacc[nt][2] * rinv1), f2tf32(oacc[nt][3] * rinv1));
        *(uint2*)&O[(b * SEQ + row0) * DMODEL + h * HDIM + dh] = v0;
        *(uint2*)&O[(b * SEQ + row0 + 8) * DMODEL + h * HDIM + dh] = v1;
    }
}

// ---------------------------------------------------------------------------
extern "C" void kernel_launch(void* const* d_in, const int* in_sizes, int n_in,
                              void* d_out, int out_size)
{
    const float* x  = (const float*)d_in[0];
    const float* wq = (const float*)d_in[1];
    const float* wk = (const float*)d_in[2];
    const float* wv = (const float*)d_in[3];
    const float* wo = (const float*)d_in[4];
    float* out = (float*)d_out;

    uint32_t *px, *pwq, *pwk, *pwv, *pwo, *pq, *pk, *pv, *pao;
    cudaGetSymbolAddress((void**)&px,  g_x);
    cudaGetSymbolAddress((void**)&pwq, g_wq);
    cudaGetSymbolAddress((void**)&pwk, g_wk);
    cudaGetSymbolAddress((void**)&pwv, g_wv);
    cudaGetSymbolAddress((void**)&pwo, g_wo);
    cudaGetSymbolAddress((void**)&pq,  g_q);
    cudaGetSymbolAddress((void**)&pk,  g_k);
    cudaGetSymbolAddress((void**)&pv,  g_v);
    cudaGetSymbolAddress((void**)&pao, g_ao);

    cudaFuncSetAttribute(gemm_qkv_kernel, cudaFuncAttributeMaxDynamicSharedMemorySize,
                         GEMM_SMEM_U32 * (int)sizeof(uint32_t));
    cudaFuncSetAttribute(gemm_o_kernel, cudaFuncAttributeMaxDynamicSharedMemorySize,
                         GEMM_SMEM_U32 * (int)sizeof(uint32_t));
    cudaFuncSetAttribute(attn_pipe_kernel, cudaFuncAttributeMaxDynamicSharedMemorySize,
                         ATT_SMEM_U32 * (int)sizeof(uint32_t));

    // fp32 -> tf32-bits conversions
    const int nx4 = MROWS * DMODEL / 4;
    const int nw4 = DMODEL * DMODEL / 4;
    cvt_tf32_kernel<<<nx4 / 256, 256>>>((const float4*)x,  (uint4*)px,  nx4);
    cvt_tf32_kernel<<<nw4 / 256, 256>>>((const float4*)wq, (uint4*)pwq, nw4);
    cvt_tf32_kernel<<<nw4 / 256, 256>>>((const float4*)wk, (uint4*)pwk, nw4);
    cvt_tf32_kernel<<<nw4 / 256, 256>>>((const float4*)wv, (uint4*)pwv, nw4);
    cvt_tf32_kernel<<<nw4 / 256, 256>>>((const float4*)wo, (uint4*)pwo, nw4);

    const size_t gsm = GEMM_SMEM_U32 * sizeof(uint32_t);
    const dim3 qkv_grid(DMODEL / 128, MROWS / 128, 3);   // (8, 64, 3)
    gemm_qkv_kernel<<<qkv_grid, 256, gsm>>>(px, pwq, pwk, pwv, pq, pk, pv);

    const dim3 agrid(SEQ / 128, BATCH * NHEADS);         // (16, 64)
    attn_pipe_kernel<<<agrid, 256, ATT_SMEM_U32 * sizeof(uint32_t)>>>(pq, pk, pv, pao);

    const dim3 ogrid(DMODEL / 128, MROWS / 128);         // (8, 64)
    gemm_o_kernel<<<ogrid, 256, gsm>>>(pao, pwo, out);
}

// round 7
// speedup vs baseline: 1.5515x; 1.5515x over previous
#include <cuda_runtime.h>
#include <cuda_bf16.h>
#include <cstdint>

#define BATCH 4
#define SEQ 2048
#define DMODEL 1024
#define NHEADS 16
#define HDIM 64
#define MROWS (BATCH * SEQ)      // 8192

// Scratch (device globals; all matmul operands live as tf32 bit patterns)
__device__ uint32_t g_x [MROWS * DMODEL];               // x, tf32 bits
__device__ uint32_t g_wq[DMODEL * DMODEL];
__device__ uint32_t g_wk[DMODEL * DMODEL];
__device__ uint32_t g_wv[DMODEL * DMODEL];
__device__ uint32_t g_wo[DMODEL * DMODEL];
__device__ uint32_t g_q [BATCH * NHEADS * SEQ * HDIM];  // [B,H,S,Dh] tf32 bits
__device__ uint32_t g_k [BATCH * NHEADS * SEQ * HDIM];
__device__ uint32_t g_v [BATCH * NHEADS * SEQ * HDIM];
__device__ uint32_t g_ao[BATCH * SEQ * DMODEL];         // [B,S,D] tf32 bits

__device__ __forceinline__ uint32_t f2tf32(float x) {
    uint32_t r;
    asm("cvt.rna.tf32.f32 %0, %1;" : "=r"(r) : "f"(x));
    return r;
}
// one-instruction 2^x (MUFU.EX2) — the R5 regression was using libm exp2f here
__device__ __forceinline__ float fexp2(float x) {
    float y;
    asm("ex2.approx.ftz.f32 %0, %1;" : "=f"(y) : "f"(x));
    return y;
}
__device__ __forceinline__ void mma_tf32(float* c, const uint32_t* a, const uint32_t* b) {
    asm volatile(
        "mma.sync.aligned.m16n8k8.row.col.f32.tf32.tf32.f32 "
        "{%0,%1,%2,%3}, {%4,%5,%6,%7}, {%8,%9}, {%0,%1,%2,%3};"
        : "+f"(c[0]), "+f"(c[1]), "+f"(c[2]), "+f"(c[3])
        : "r"(a[0]), "r"(a[1]), "r"(a[2]), "r"(a[3]), "r"(b[0]), "r"(b[1]));
}
__device__ __forceinline__ uint32_t smem_u32(const void* p) {
    return (uint32_t)__cvta_generic_to_shared(p);
}
__device__ __forceinline__ void cp16(uint32_t dst, const void* src) {
    asm volatile("cp.async.cg.shared.global [%0], [%1], 16;" :: "r"(dst), "l"(src));
}
__device__ __forceinline__ void cp_commit() { asm volatile("cp.async.commit_group;"); }
template<int N> __device__ __forceinline__ void cp_wait() {
    asm volatile("cp.async.wait_group %0;" :: "n"(N));
}

// ---------------------------------------------------------------------------
// fp32 -> tf32-bits elementwise convert
// ---------------------------------------------------------------------------
__global__ __launch_bounds__(256) void cvt_tf32_kernel(
    const float4* __restrict__ in, uint4* __restrict__ out, int n4)
{
    const int i = blockIdx.x * blockDim.x + threadIdx.x;
    if (i < n4) {
        float4 v = in[i];
        uint4 o;
        o.x = f2tf32(v.x); o.y = f2tf32(v.y);
        o.z = f2tf32(v.z); o.w = f2tf32(v.w);
        out[i] = o;
    }
}

// ---------------------------------------------------------------------------
// Pipelined tf32 GEMM core (operands already tf32 bits, no cvt in loop).
// C = A[M,K] * B[N,K]^T, 128x128 block, BK=16, 4-stage cp.async.
// ---------------------------------------------------------------------------
#define GKS 20
#define GEMM_SMEM_U32 (2 * 4 * 128 * GKS)

struct GemmAcc { float a[4][4][4]; };

__device__ __forceinline__ void gemm_core(
    const uint32_t* __restrict__ A, const uint32_t* __restrict__ Bw,
    uint32_t* As, uint32_t* Bs, int bm, int bn, GemmAcc& G)
{
    const int tid  = threadIdx.x;
    const int warp = tid >> 5;
    const int lane = tid & 31;
    const int wm = warp >> 2;
    const int wn = warp & 3;
    const int r = lane >> 2;
    const int c = lane & 3;

    const int lch = tid & 3;
    const int lrw = tid >> 2;
    const uint32_t* Agl = A  + (bm + lrw) * DMODEL + lch * 4;
    const uint32_t* Bgl = Bw + (bn + lrw) * DMODEL + lch * 4;
    const uint32_t aB = smem_u32(As);
    const uint32_t bB = smem_u32(Bs);
    const uint32_t dOff = ((uint32_t)(lrw * GKS + lch * 4)) * 4u;
    const uint32_t rowHalf = 64u * GKS * 4u;

    auto issue = [&](int s) {
        const int buf = s & 3;
        const int k0 = s << 4;
        const uint32_t sb = (uint32_t)(buf * 128 * GKS) * 4u;
        cp16(aB + sb + dOff, Agl + k0);
        cp16(aB + sb + dOff + rowHalf, Agl + 64 * DMODEL + k0);
        cp16(bB + sb + dOff, Bgl + k0);
        cp16(bB + sb + dOff + rowHalf, Bgl + 64 * DMODEL + k0);
    };

    issue(0); cp_commit();
    issue(1); cp_commit();
    issue(2); cp_commit();

#pragma unroll
    for (int i = 0; i < 4; i++)
#pragma unroll
        for (int j = 0; j < 4; j++)
#pragma unroll
            for (int q = 0; q < 4; q++) G.a[i][j][q] = 0.0f;

    for (int t = 0; t < 64; t++) {
        cp_wait<2>();
        __syncthreads();
        if (t + 3 < 64) issue(t + 3);
        cp_commit();

        const uint32_t* Ab = As + (t & 3) * 128 * GKS;
        const uint32_t* Bb = Bs + (t & 3) * 128 * GKS;
#pragma unroll
        for (int ks = 0; ks < 16; ks += 8) {
            uint32_t af[4][4], bf[4][2];
#pragma unroll
            for (int mt = 0; mt < 4; mt++) {
                const int m = wm * 64 + mt * 16 + r;
                af[mt][0] = Ab[m * GKS + ks + c];
                af[mt][1] = Ab[(m + 8) * GKS + ks + c];
                af[mt][2] = Ab[m * GKS + ks + c + 4];
                af[mt][3] = Ab[(m + 8) * GKS + ks + c + 4];
            }
#pragma unroll
            for (int nt = 0; nt < 4; nt++) {
                const int n = wn * 32 + nt * 8 + r;
                bf[nt][0] = Bb[n * GKS + ks + c];
                bf[nt][1] = Bb[n * GKS + ks + c + 4];
            }
#pragma unroll
            for (int mt = 0; mt < 4; mt++)
#pragma unroll
                for (int nt = 0; nt < 4; nt++)
                    mma_tf32(G.a[mt][nt], af[mt], bf[nt]);
        }
    }
}

// Fused QKV projection: gridDim.z selects weight/output; scatter tf32 bits.
__global__ __launch_bounds__(256, 2) void gemm_qkv_kernel(
    const uint32_t* __restrict__ X,
    const uint32_t* __restrict__ Wq, const uint32_t* __restrict__ Wk,
    const uint32_t* __restrict__ Wv,
    uint32_t* __restrict__ Oq, uint32_t* __restrict__ Ok,
    uint32_t* __restrict__ Ov)
{
    extern __shared__ uint32_t gsm[];
    const uint32_t* W = (blockIdx.z == 0) ? Wq : (blockIdx.z == 1) ? Wk : Wv;
    uint32_t* C = (blockIdx.z == 0) ? Oq : (blockIdx.z == 1) ? Ok : Ov;

    const int bm = blockIdx.y << 7;
    const int bn = blockIdx.x << 7;
    GemmAcc G;
    gemm_core(X, W, gsm, gsm + 4 * 128 * GKS, bm, bn, G);

    const int lane = threadIdx.x & 31;
    const int warp = threadIdx.x >> 5;
    const int r = lane >> 2, c = lane & 3;
    const int wm = warp >> 2, wn = warp & 3;
#pragma unroll
    for (int mt = 0; mt < 4; mt++) {
        const int m0 = bm + wm * 64 + mt * 16 + r;
#pragma unroll
        for (int nt = 0; nt < 4; nt++) {
            const int n = bn + wn * 32 + nt * 8 + c * 2;
            const int h = n >> 6;
            const int dh = n & 63;
#pragma unroll
            for (int half = 0; half < 2; half++) {
                const int m = m0 + half * 8;
                const int b = m >> 11;
                const int s = m & (SEQ - 1);
                uint2 v = make_uint2(f2tf32(G.a[mt][nt][half * 2]),
                                     f2tf32(G.a[mt][nt][half * 2 + 1]));
                *(uint2*)&C[((b * NHEADS + h) * SEQ + s) * HDIM + dh] = v;
            }
        }
    }
}

// O projection: fp32 row-major output.
__global__ __launch_bounds__(256, 2) void gemm_o_kernel(
    const uint32_t* __restrict__ A, const uint32_t* __restrict__ W,
    float* __restrict__ C)
{
    extern __shared__ uint32_t gsm[];
    const int bm = blockIdx.y << 7;
    const int bn = blockIdx.x << 7;
    GemmAcc G;
    gemm_core(A, W, gsm, gsm + 4 * 128 * GKS, bm, bn, G);

    const int lane = threadIdx.x & 31;
    const int warp = threadIdx.x >> 5;
    const int r = lane >> 2, c = lane & 3;
    const int wm = warp >> 2, wn = warp & 3;
#pragma unroll
    for (int mt = 0; mt < 4; mt++) {
        const int m0 = bm + wm * 64 + mt * 16 + r;
#pragma unroll
        for (int nt = 0; nt < 4; nt++) {
            const int n = bn + wn * 32 + nt * 8 + c * 2;
#pragma unroll
            for (int half = 0; half < 2; half++) {
                const int m = m0 + half * 8;
                float2 v = make_float2(G.a[mt][nt][half * 2],
                                       G.a[mt][nt][half * 2 + 1]);
                *(float2*)&C[m * DMODEL + n] = v;
            }
        }
    }
}

// ---------------------------------------------------------------------------
// Pipelined tf32 flash attention (causal), operands are tf32 bits.
// 256 threads = 8 warps; q-tile 128, kv-tile 64, double-buffered cp.async.
// Base-2 softmax via MUFU ex2: Q pre-scaled by 0.125*log2(e).
// ---------------------------------------------------------------------------
#define AKS 68
#define AVS 72
#define APS 68
#define ATT_SMEM_U32 (2 * 64 * AKS + 2 * 64 * AVS + 128 * APS)
#define QSCALE (0.125f * 1.4426950408889634f)

__global__ __launch_bounds__(256, 2) void attn_pipe_kernel(
    const uint32_t* __restrict__ Q, const uint32_t* __restrict__ K,
    const uint32_t* __restrict__ V, uint32_t* __restrict__ O)
{
    extern __shared__ uint32_t smu[];
    uint32_t* Ks = smu;                              // [2][64][68]
    uint32_t* Vs = smu + 2 * 64 * AKS;               // [2][64][72]
    uint32_t* Pu = smu + 2 * 64 * AKS + 2 * 64 * AVS; // [128][68]

    const int tid  = threadIdx.x;
    const int warp = tid >> 5;
    const int lane = tid & 31;
    const int r = lane >> 2;
    const int c = lane & 3;

    const int bh = blockIdx.y;
    const int QT = gridDim.x - 1 - blockIdx.x;    // longest first
    const int q0 = QT << 7;
    const uint32_t* Qb = Q + bh * (SEQ * HDIM);
    const uint32_t* Kb = K + bh * (SEQ * HDIM);
    const uint32_t* Vb = V + bh * (SEQ * HDIM);

    // ---- stage Q tile (128x64 bits) into Pu ----
    {
        const int qrow = tid >> 1;
        const int qcol = (tid & 1) << 5;
#pragma unroll
        for (int cc = 0; cc < 32; cc += 4)
            *(uint4*)&Pu[qrow * APS + qcol + cc] =
                *(const uint4*)&Qb[(q0 + qrow) * HDIM + qcol + cc];
    }
    __syncthreads();

    const int qr = warp * 16 + r;
    uint32_t qf[8][4];
#pragma unroll
    for (int ks = 0; ks < 8; ks++) {
        const int d = ks * 8 + c;
        qf[ks][0] = f2tf32(QSCALE * __uint_as_float(Pu[qr * APS + d]));
        qf[ks][1] = f2tf32(QSCALE * __uint_as_float(Pu[(qr + 8) * APS + d]));
        qf[ks][2] = f2tf32(QSCALE * __uint_as_float(Pu[qr * APS + d + 4]));
        qf[ks][3] = f2tf32(QSCALE * __uint_as_float(Pu[(qr + 8) * APS + d + 4]));
    }

    // ---- KV loader (cp.async) ----
    const int ch  = tid & 15;
    const int lr0 = tid >> 4;
    const uint32_t ksB = smem_u32(Ks);
    const uint32_t vsB = smem_u32(Vs);

    auto issue_kv = [&](int t) {
        const int buf = t & 1;
        const int k0 = t << 6;
#pragma unroll
        for (int j = 0; j < 4; j++) {
            const int row = lr0 + 16 * j;
            cp16(ksB + ((buf * 64 + row) * AKS + ch * 4) * 4u,
                 Kb + (k0 + row) * HDIM + ch * 4);
            cp16(vsB + ((buf * 64 + row) * AVS + ch * 4) * 4u,
                 Vb + (k0 + row) * HDIM + ch * 4);
        }
    };

    issue_kv(0); cp_commit();

    float oacc[8][4];
#pragma unroll
    for (int nt = 0; nt < 8; nt++)
#pragma unroll
        for (int j = 0; j < 4; j++) oacc[nt][j] = 0.0f;
    float mrun[2] = {-1e30f, -1e30f};
    float lrun[2] = {0.0f, 0.0f};

    const int T = 2 * QT + 1;
    for (int t = 0; t <= T; t++) {
        cp_wait<0>();
        __syncthreads();
        if (t < T) issue_kv(t + 1);
        cp_commit();

        const uint32_t* Kt = Ks + (t & 1) * 64 * AKS;
        const uint32_t* Vt = Vs + (t & 1) * 64 * AVS;

        // ---- scores (log2-scaled) ----
        float sacc[8][4];
#pragma unroll
        for (int nt = 0; nt < 8; nt++)
#pragma unroll
            for (int j = 0; j < 4; j++) sacc[nt][j] = 0.0f;
#pragma unroll
        for (int ks = 0; ks < 8; ks++) {
#pragma unroll
            for (int nt = 0; nt < 8; nt++) {
                uint32_t kb[2];
                const int base = (nt * 8 + r) * AKS + ks * 8 + c;
                kb[0] = Kt[base];
                kb[1] = Kt[base + 4];
                mma_tf32(sacc[nt], qf[ks], kb);
            }
        }

        // ---- causal mask (diagonal region only) ----
        if (t >= 2 * QT) {
            const int kbase = t << 6;
#pragma unroll
            for (int nt = 0; nt < 8; nt++)
#pragma unroll
                for (int j = 0; j < 4; j++) {
                    const int kg = kbase + nt * 8 + 2 * c + (j & 1);
                    const int qg = q0 + warp * 16 + r + (j >> 1) * 8;
                    if (kg > qg) sacc[nt][j] = -1e30f;
                }
        }

        // ---- online softmax (base 2, MUFU ex2) ----
#pragma unroll
        for (int hh = 0; hh < 2; hh++) {
            float tm = -1e30f;
#pragma unroll
            for (int nt = 0; nt < 8; nt++)
                tm = fmaxf(tm, fmaxf(sacc[nt][2 * hh], sacc[nt][2 * hh + 1]));
            tm = fmaxf(tm, __shfl_xor_sync(0xffffffffu, tm, 1));
            tm = fmaxf(tm, __shfl_xor_sync(0xffffffffu, tm, 2));
            const float mnew  = fmaxf(mrun[hh], tm);
            const float alpha = fexp2(mrun[hh] - mnew);
            float ls = 0.0f;
            const int prow = (warp * 16 + r + hh * 8) * APS;
#pragma unroll
            for (int nt = 0; nt < 8; nt++) {
                const float p0 = fexp2(sacc[nt][2 * hh] - mnew);
                const float p1 = fexp2(sacc[nt][2 * hh + 1] - mnew);
                ls += p0 + p1;
                uint2 pv = make_uint2(f2tf32(p0), f2tf32(p1));
                *(uint2*)&Pu[prow + nt * 8 + 2 * c] = pv;
            }
            ls += __shfl_xor_sync(0xffffffffu, ls, 1);
            ls += __shfl_xor_sync(0xffffffffu, ls, 2);
            lrun[hh] = lrun[hh] * alpha + ls;
            mrun[hh] = mnew;
#pragma unroll
            for (int nt = 0; nt < 8; nt++) {
                oacc[nt][2 * hh]     *= alpha;
                oacc[nt][2 * hh + 1] *= alpha;
            }
        }
        __syncwarp();   // P region is warp-local: order STS before LDS

        // ---- O += P V ----
#pragma unroll
        for (int ks = 0; ks < 8; ks++) {
            uint32_t pf[4];
            const int d = ks * 8 + c;
            pf[0] = Pu[qr * APS + d];
            pf[1] = Pu[(qr + 8) * APS + d];
            pf[2] = Pu[qr * APS + d + 4];
            pf[3] = Pu[(qr + 8) * APS + d + 4];
#pragma unroll
            for (int nt = 0; nt < 8; nt++) {
                uint32_t vb[2];
                vb[0] = Vt[(ks * 8 + c) * AVS + nt * 8 + r];
                vb[1] = Vt[(ks * 8 + c + 4) * AVS + nt * 8 + r];
                mma_tf32(oacc[nt], pf, vb);
            }
        }
    }

    // ---- epilogue: normalize, write tf32 bits to [B,S,D] ----
    const float rinv0 = 1.0f / lrun[0];
    const float rinv1 = 1.0f / lrun[1];
    const int b = bh >> 4, h = bh & 15;
    const int row0 = q0 + qr;
#pragma unroll
    for (int nt = 0; nt < 8; nt++) {
        const int dh = nt * 8 + 2 * c;
        uint2 v0 = make_uint2(f2tf32(oacc[nt][0] * rinv0), f2tf32(oacc[nt][1] * rinv0));
        uint2 v1 = make_uint2(f2tf32(oacc[nt][2] * rinv1), f2tf32(oacc[nt][3] * rinv1));
        *(uint2*)&O[(b * SEQ + row0) * DMODEL + h * HDIM + dh] = v0;
        *(uint2*)&O[(b * SEQ + row0 + 8) * DMODEL + h * HDIM + dh] = v1;
    }
}

// ---------------------------------------------------------------------------
extern "C" void kernel_launch(void* const* d_in, const int* in_sizes, int n_in,
                              void* d_out, int out_size)
{
    const float* x  = (const float*)d_in[0];
    const float* wq = (const float*)d_in[1];
    const float* wk = (const float*)d_in[2];
    const float* wv = (const float*)d_in[3];
    const float* wo = (const float*)d_in[4];
    float* out = (float*)d_out;

    uint32_t *px, *pwq, *pwk, *pwv, *pwo, *pq, *pk, *pv, *pao;
    cudaGetSymbolAddress((void**)&px,  g_x);
    cudaGetSymbolAddress((void**)&pwq, g_wq);
    cudaGetSymbolAddress((void**)&pwk, g_wk);
    cudaGetSymbolAddress((void**)&pwv, g_wv);
    cudaGetSymbolAddress((void**)&pwo, g_wo);
    cudaGetSymbolAddress((void**)&pq,  g_q);
    cudaGetSymbolAddress((void**)&pk,  g_k);
    cudaGetSymbolAddress((void**)&pv,  g_v);
    cudaGetSymbolAddress((void**)&pao, g_ao);

    cudaFuncSetAttribute(gemm_qkv_kernel, cudaFuncAttributeMaxDynamicSharedMemorySize,
                         GEMM_SMEM_U32 * (int)sizeof(uint32_t));
    cudaFuncSetAttribute(gemm_o_kernel, cudaFuncAttributeMaxDynamicSharedMemorySize,
                         GEMM_SMEM_U32 * (int)sizeof(uint32_t));
    cudaFuncSetAttribute(attn_pipe_kernel, cudaFuncAttributeMaxDynamicSharedMemorySize,
                         ATT_SMEM_U32 * (int)sizeof(uint32_t));

    // fp32 -> tf32-bits conversions
    const int nx4 = MROWS * DMODEL / 4;
    const int nw4 = DMODEL * DMODEL / 4;
    cvt_tf32_kernel<<<nx4 / 256, 256>>>((const float4*)x,  (uint4*)px,  nx4);
    cvt_tf32_kernel<<<nw4 / 256, 256>>>((const float4*)wq, (uint4*)pwq, nw4);
    cvt_tf32_kernel<<<nw4 / 256, 256>>>((const float4*)wk, (uint4*)pwk, nw4);
    cvt_tf32_kernel<<<nw4 / 256, 256>>>((const float4*)wv, (uint4*)pwv, nw4);
    cvt_tf32_kernel<<<nw4 / 256, 256>>>((const float4*)wo, (uint4*)pwo, nw4);

    const size_t gsm = GEMM_SMEM_U32 * sizeof(uint32_t);
    const dim3 qkv_grid(DMODEL / 128, MROWS / 128, 3);   // (8, 64, 3)
    gemm_qkv_kernel<<<qkv_grid, 256, gsm>>>(px, pwq, pwk, pwv, pq, pk, pv);

    const dim3 agrid(SEQ / 128, BATCH * NHEADS);         // (16, 64)
    attn_pipe_kernel<<<agrid, 256, ATT_SMEM_U32 * sizeof(uint32_t)>>>(pq, pk, pv, pao);

    const dim3 ogrid(DMODEL / 128, MROWS / 128);         // (8, 64)
    gemm_o_kernel<<<ogrid, 256, gsm>>>(pao, pwo, out);
}

// round 8
// speedup vs baseline: 1.7732x; 1.1429x over previous
#include <cuda_runtime.h>
#include <cuda_bf16.h>
#include <cstdint>

#define BATCH 4
#define SEQ 2048
#define DMODEL 1024
#define NHEADS 16
#define HDIM 64
#define MROWS (BATCH * SEQ)      // 8192

// Scratch (device globals; all matmul operands live as tf32 bit patterns)
__device__ uint32_t g_x [MROWS * DMODEL];               // x, tf32 bits
__device__ uint32_t g_wq[DMODEL * DMODEL];
__device__ uint32_t g_wk[DMODEL * DMODEL];
__device__ uint32_t g_wv[DMODEL * DMODEL];
__device__ uint32_t g_wo[DMODEL * DMODEL];
__device__ uint32_t g_q [BATCH * NHEADS * SEQ * HDIM];  // [B,H,S,Dh] tf32 bits
__device__ uint32_t g_k [BATCH * NHEADS * SEQ * HDIM];  // [B,H,S,Dh]
__device__ uint32_t g_v [BATCH * NHEADS * HDIM * SEQ];  // [B,H,Dh,S]  (transposed!)
__device__ uint32_t g_ao[BATCH * SEQ * DMODEL];         // [B,S,D] tf32 bits

__device__ __forceinline__ uint32_t f2tf32(float x) {
    uint32_t r;
    asm("cvt.rna.tf32.f32 %0, %1;" : "=r"(r) : "f"(x));
    return r;
}
__device__ __forceinline__ float fexp2(float x) {
    float y;
    asm("ex2.approx.ftz.f32 %0, %1;" : "=f"(y) : "f"(x));
    return y;
}
__device__ __forceinline__ void mma_tf32(float* c, const uint32_t* a, const uint32_t* b) {
    asm volatile(
        "mma.sync.aligned.m16n8k8.row.col.f32.tf32.tf32.f32 "
        "{%0,%1,%2,%3}, {%4,%5,%6,%7}, {%8,%9}, {%0,%1,%2,%3};"
        : "+f"(c[0]), "+f"(c[1]), "+f"(c[2]), "+f"(c[3])
        : "r"(a[0]), "r"(a[1]), "r"(a[2]), "r"(a[3]), "r"(b[0]), "r"(b[1]));
}
// ldmatrix x4 on b16 tiles == four 8x8 tf32 tiles in native frag layout
__device__ __forceinline__ void ldsm4(uint32_t& r0, uint32_t& r1,
                                      uint32_t& r2, uint32_t& r3, uint32_t addr) {
    asm volatile("ldmatrix.sync.aligned.m8n8.x4.shared.b16 {%0,%1,%2,%3}, [%4];"
                 : "=r"(r0), "=r"(r1), "=r"(r2), "=r"(r3) : "r"(addr));
}
__device__ __forceinline__ uint32_t smem_u32(const void* p) {
    return (uint32_t)__cvta_generic_to_shared(p);
}
__device__ __forceinline__ void cp16(uint32_t dst, const void* src) {
    asm volatile("cp.async.cg.shared.global [%0], [%1], 16;" :: "r"(dst), "l"(src));
}
__device__ __forceinline__ void cp_commit() { asm volatile("cp.async.commit_group;"); }
template<int N> __device__ __forceinline__ void cp_wait() {
    asm volatile("cp.async.wait_group %0;" :: "n"(N));
}

// ---------------------------------------------------------------------------
// fp32 -> tf32-bits elementwise convert
// ---------------------------------------------------------------------------
__global__ __launch_bounds__(256) void cvt_tf32_kernel(
    const float4* __restrict__ in, uint4* __restrict__ out, int n4)
{
    const int i = blockIdx.x * blockDim.x + threadIdx.x;
    if (i < n4) {
        float4 v = in[i];
        uint4 o;
        o.x = f2tf32(v.x); o.y = f2tf32(v.y);
        o.z = f2tf32(v.z); o.w = f2tf32(v.w);
        out[i] = o;
    }
}

// ---------------------------------------------------------------------------
// Pipelined tf32 GEMM core, ldmatrix fragment loads.
// C = A[M,K] * B[N,K]^T, 128x128 block, BK=16, 4-stage cp.async.
// ---------------------------------------------------------------------------
#define GKS 20
#define GEMM_SMEM_U32 (2 * 4 * 128 * GKS)

struct GemmAcc { float a[4][4][4]; };

__device__ __forceinline__ void gemm_core(
    const uint32_t* __restrict__ A, const uint32_t* __restrict__ Bw,
    uint32_t* As, uint32_t* Bs, int bm, int bn, GemmAcc& G)
{
    const int tid  = threadIdx.x;
    const int warp = tid >> 5;
    const int lane = tid & 31;
    const int wm = warp >> 2;
    const int wn = warp & 3;

    // ldmatrix lane offsets (in 32-bit words)
    const int g  = lane >> 3;
    const int ri = lane & 7;
    const int offA = ((g & 1) * 8 + ri) * GKS + (g >> 1) * 4;  // A: m-rows, k-chunks
    const int offB = ((g >> 1) * 8 + ri) * GKS + (g & 1) * 4;  // B: n-rows, k-chunks

    const int lch = tid & 3;
    const int lrw = tid >> 2;
    const uint32_t* Agl = A  + (bm + lrw) * DMODEL + lch * 4;
    const uint32_t* Bgl = Bw + (bn + lrw) * DMODEL + lch * 4;
    const uint32_t aB = smem_u32(As);
    const uint32_t bB = smem_u32(Bs);
    const uint32_t dOff = ((uint32_t)(lrw * GKS + lch * 4)) * 4u;
    const uint32_t rowHalf = 64u * GKS * 4u;

    auto issue = [&](int s) {
        const int buf = s & 3;
        const int k0 = s << 4;
        const uint32_t sb = (uint32_t)(buf * 128 * GKS) * 4u;
        cp16(aB + sb + dOff, Agl + k0);
        cp16(aB + sb + dOff + rowHalf, Agl + 64 * DMODEL + k0);
        cp16(bB + sb + dOff, Bgl + k0);
        cp16(bB + sb + dOff + rowHalf, Bgl + 64 * DMODEL + k0);
    };

    issue(0); cp_commit();
    issue(1); cp_commit();
    issue(2); cp_commit();

#pragma unroll
    for (int i = 0; i < 4; i++)
#pragma unroll
        for (int j = 0; j < 4; j++)
#pragma unroll
            for (int q = 0; q < 4; q++) G.a[i][j][q] = 0.0f;

    for (int t = 0; t < 64; t++) {
        cp_wait<2>();
        __syncthreads();
        if (t + 3 < 64) issue(t + 3);
        cp_commit();

        const uint32_t tb = (uint32_t)((t & 3) * 128 * GKS) * 4u;
#pragma unroll
        for (int ks = 0; ks < 16; ks += 8) {
            uint32_t af[4][4], bf[4][2];
#pragma unroll
            for (int mt = 0; mt < 4; mt++)
                ldsm4(af[mt][0], af[mt][1], af[mt][2], af[mt][3],
                      aB + tb + (uint32_t)(((wm * 64 + mt * 16) * GKS) + ks + offA) * 4u);
#pragma unroll
            for (int ntp = 0; ntp < 2; ntp++)
                ldsm4(bf[2 * ntp][0], bf[2 * ntp][1], bf[2 * ntp + 1][0], bf[2 * ntp + 1][1],
                      bB + tb + (uint32_t)(((wn * 32 + ntp * 16) * GKS) + ks + offB) * 4u);
#pragma unroll
            for (int mt = 0; mt < 4; mt++)
#pragma unroll
                for (int nt = 0; nt < 4; nt++)
                    mma_tf32(G.a[mt][nt], af[mt], bf[nt]);
        }
    }
}

// Fused QKV projection: gridDim.z selects weight/output; scatter tf32 bits.
// z==2 (V) scatters TRANSPOSED to [B,H,Dh,S] for ldmatrix-friendly attention.
__global__ __launch_bounds__(256, 2) void gemm_qkv_kernel(
    const uint32_t* __restrict__ X,
    const uint32_t* __restrict__ Wq, const uint32_t* __restrict__ Wk,
    const uint32_t* __restrict__ Wv,
    uint32_t* __restrict__ Oq, uint32_t* __restrict__ Ok,
    uint32_t* __restrict__ Ov)
{
    extern __shared__ uint32_t gsm[];
    const int zi = blockIdx.z;
    const uint32_t* W = (zi == 0) ? Wq : (zi == 1) ? Wk : Wv;
    uint32_t* C = (zi == 0) ? Oq : (zi == 1) ? Ok : Ov;

    const int bm = blockIdx.y << 7;
    const int bn = blockIdx.x << 7;
    GemmAcc G;
    gemm_core(X, W, gsm, gsm + 4 * 128 * GKS, bm, bn, G);

    const int lane = threadIdx.x & 31;
    const int warp = threadIdx.x >> 5;
    const int r = lane >> 2, c = lane & 3;
    const int wm = warp >> 2, wn = warp & 3;
#pragma unroll
    for (int mt = 0; mt < 4; mt++) {
        const int m0 = bm + wm * 64 + mt * 16 + r;
#pragma unroll
        for (int nt = 0; nt < 4; nt++) {
            const int n = bn + wn * 32 + nt * 8 + c * 2;
            const int h = n >> 6;
            const int dh = n & 63;
#pragma unroll
            for (int half = 0; half < 2; half++) {
                const int m = m0 + half * 8;
                const int b = m >> 11;
                const int s = m & (SEQ - 1);
                const uint32_t v0 = f2tf32(G.a[mt][nt][half * 2]);
                const uint32_t v1 = f2tf32(G.a[mt][nt][half * 2 + 1]);
                if (zi == 2) {
                    // [B,H,Dh,S]
                    const int base = ((b * NHEADS + h) * HDIM + dh) * SEQ + s;
                    C[base] = v0;
                    C[base + SEQ] = v1;
                } else {
                    *(uint2*)&C[((b * NHEADS + h) * SEQ + s) * HDIM + dh] =
                        make_uint2(v0, v1);
                }
            }
        }
    }
}

// O projection: fp32 row-major output.
__global__ __launch_bounds__(256, 2) void gemm_o_kernel(
    const uint32_t* __restrict__ A, const uint32_t* __restrict__ W,
    float* __restrict__ C)
{
    extern __shared__ uint32_t gsm[];
    const int bm = blockIdx.y << 7;
    const int bn = blockIdx.x << 7;
    GemmAcc G;
    gemm_core(A, W, gsm, gsm + 4 * 128 * GKS, bm, bn, G);

    const int lane = threadIdx.x & 31;
    const int warp = threadIdx.x >> 5;
    const int r = lane >> 2, c = lane & 3;
    const int wm = warp >> 2, wn = warp & 3;
#pragma unroll
    for (int mt = 0; mt < 4; mt++) {
        const int m0 = bm + wm * 64 + mt * 16 + r;
#pragma unroll
        for (int nt = 0; nt < 4; nt++) {
            const int n = bn + wn * 32 + nt * 8 + c * 2;
#pragma unroll
            for (int half = 0; half < 2; half++) {
                const int m = m0 + half * 8;
                float2 v = make_float2(G.a[mt][nt][half * 2],
                                       G.a[mt][nt][half * 2 + 1]);
                *(float2*)&C[m * DMODEL + n] = v;
            }
        }
    }
}

// ---------------------------------------------------------------------------
// Pipelined tf32 flash attention (causal), ldmatrix fragment loads.
// 256 threads = 8 warps; q-tile 128, kv-tile 64, double-buffered cp.async.
// K smem [kseq][dh]; V smem [dh][kseq] (from transposed g_v); P smem [q][kseq].
// ---------------------------------------------------------------------------
#define AKS 68
#define AVS 68
#define APS 68
#define ATT_SMEM_U32 (2 * 64 * AKS + 2 * 64 * AVS + 128 * APS)
#define QSCALE (0.125f * 1.4426950408889634f)

__global__ __launch_bounds__(256, 2) void attn_pipe_kernel(
    const uint32_t* __restrict__ Q, const uint32_t* __restrict__ K,
    const uint32_t* __restrict__ V, uint32_t* __restrict__ O)
{
    extern __shared__ uint32_t smu[];
    uint32_t* Ks = smu;                               // [2][64][AKS]  rows=kseq
    uint32_t* Vs = smu + 2 * 64 * AKS;                // [2][64][AVS]  rows=dh
    uint32_t* Pu = smu + 2 * 64 * AKS + 2 * 64 * AVS; // [128][APS]    rows=q

    const int tid  = threadIdx.x;
    const int warp = tid >> 5;
    const int lane = tid & 31;
    const int r = lane >> 2;
    const int c = lane & 3;
    const int g  = lane >> 3;
    const int ri = lane & 7;

    // ldmatrix lane offsets (32-bit words)
    const int offK = ((g >> 1) * 8 + ri) * AKS + (g & 1) * 4;  // B-frag from [n][k]
    const int offV = ((g >> 1) * 8 + ri) * AVS + (g & 1) * 4;  // B-frag from [n][k]
    const int offP = ((g & 1) * 8 + ri) * APS + (g >> 1) * 4;  // A-frag from [m][k]

    const int bh = blockIdx.y;
    const int QT = gridDim.x - 1 - blockIdx.x;    // longest first
    const int q0 = QT << 7;
    const uint32_t* Qb = Q + bh * (SEQ * HDIM);
    const uint32_t* Kb = K + bh * (SEQ * HDIM);
    const uint32_t* Vb = V + bh * (HDIM * SEQ);   // [Dh][S]

    // ---- stage Q tile (128x64 bits) into Pu ----
    {
        const int qrow = tid >> 1;
        const int qcol = (tid & 1) << 5;
#pragma unroll
        for (int cc = 0; cc < 32; cc += 4)
            *(uint4*)&Pu[qrow * APS + qcol + cc] =
                *(const uint4*)&Qb[(q0 + qrow) * HDIM + qcol + cc];
    }
    __syncthreads();

    const int qr = warp * 16 + r;
    uint32_t qf[8][4];
#pragma unroll
    for (int ks = 0; ks < 8; ks++) {
        const int d = ks * 8 + c;
        qf[ks][0] = f2tf32(QSCALE * __uint_as_float(Pu[qr * APS + d]));
        qf[ks][1] = f2tf32(QSCALE * __uint_as_float(Pu[(qr + 8) * APS + d]));
        qf[ks][2] = f2tf32(QSCALE * __uint_as_float(Pu[qr * APS + d + 4]));
        qf[ks][3] = f2tf32(QSCALE * __uint_as_float(Pu[(qr + 8) * APS + d + 4]));
    }

    // ---- KV loader (cp.async): 16 lanes x 16B cover a 256B row ----
    const int ch  = tid & 15;
    const int lr0 = tid >> 4;
    const uint32_t ksB = smem_u32(Ks);
    const uint32_t vsB = smem_u32(Vs);
    const uint32_t puB = smem_u32(Pu);

    auto issue_kv = [&](int t) {
        const int buf = t & 1;
        const int k0 = t << 6;
#pragma unroll
        for (int j = 0; j < 4; j++) {
            const int row = lr0 + 16 * j;
            cp16(ksB + ((buf * 64 + row) * AKS + ch * 4) * 4u,
                 Kb + (k0 + row) * HDIM + ch * 4);             // K row = kseq
            cp16(vsB + ((buf * 64 + row) * AVS + ch * 4) * 4u,
                 Vb + row * SEQ + k0 + ch * 4);                // V row = dh
        }
    };

    issue_kv(0); cp_commit();

    float oacc[8][4];
#pragma unroll
    for (int nt = 0; nt < 8; nt++)
#pragma unroll
        for (int j = 0; j < 4; j++) oacc[nt][j] = 0.0f;
    float mrun[2] = {-1e30f, -1e30f};
    float lrun[2] = {0.0f, 0.0f};

    const int T = 2 * QT + 1;
    for (int t = 0; t <= T; t++) {
        cp_wait<0>();
        __syncthreads();
        if (t < T) issue_kv(t + 1);
        cp_commit();

        const uint32_t ktB = ksB + (uint32_t)((t & 1) * 64 * AKS) * 4u;
        const uint32_t vtB = vsB + (uint32_t)((t & 1) * 64 * AVS) * 4u;

        // ---- scores (log2-scaled): S = Q K^T ----
        float sacc[8][4];
#pragma unroll
        for (int nt = 0; nt < 8; nt++)
#pragma unroll
            for (int j = 0; j < 4; j++) sacc[nt][j] = 0.0f;
#pragma unroll
        for (int ks = 0; ks < 8; ks++) {
            uint32_t kf[8][2];
#pragma unroll
            for (int ntp = 0; ntp < 4; ntp++)
                ldsm4(kf[2 * ntp][0], kf[2 * ntp][1],
                      kf[2 * ntp + 1][0], kf[2 * ntp + 1][1],
                      ktB + (uint32_t)(ntp * 16 * AKS + ks * 8 + offK) * 4u);
#pragma unroll
            for (int nt = 0; nt < 8; nt++)
                mma_tf32(sacc[nt], qf[ks], kf[nt]);
        }

        // ---- causal mask (diagonal region only) ----
        if (t >= 2 * QT) {
            const int kbase = t << 6;
#pragma unroll
            for (int nt = 0; nt < 8; nt++)
#pragma unroll
                for (int j = 0; j < 4; j++) {
                    const int kg = kbase + nt * 8 + 2 * c + (j & 1);
                    const int qg = q0 + warp * 16 + r + (j >> 1) * 8;
                    if (kg > qg) sacc[nt][j] = -1e30f;
                }
        }

        // ---- online softmax (base 2, MUFU ex2) ----
#pragma unroll
        for (int hh = 0; hh < 2; hh++) {
            float tm = -1e30f;
#pragma unroll
            for (int nt = 0; nt < 8; nt++)
                tm = fmaxf(tm, fmaxf(sacc[nt][2 * hh], sacc[nt][2 * hh + 1]));
            tm = fmaxf(tm, __shfl_xor_sync(0xffffffffu, tm, 1));
            tm = fmaxf(tm, __shfl_xor_sync(0xffffffffu, tm, 2));
            const float mnew  = fmaxf(mrun[hh], tm);
            const float alpha = fexp2(mrun[hh] - mnew);
            float ls = 0.0f;
            const int prow = (warp * 16 + r + hh * 8) * APS;
#pragma unroll
            for (int nt = 0; nt < 8; nt++) {
                const float p0 = fexp2(sacc[nt][2 * hh] - mnew);
                const float p1 = fexp2(sacc[nt][2 * hh + 1] - mnew);
                ls += p0 + p1;
                uint2 pv = make_uint2(f2tf32(p0), f2tf32(p1));
                *(uint2*)&Pu[prow + nt * 8 + 2 * c] = pv;
            }
            ls += __shfl_xor_sync(0xffffffffu, ls, 1);
            ls += __shfl_xor_sync(0xffffffffu, ls, 2);
            lrun[hh] = lrun[hh] * alpha + ls;
            mrun[hh] = mnew;
#pragma unroll
            for (int nt = 0; nt < 8; nt++) {
                oacc[nt][2 * hh]     *= alpha;
                oacc[nt][2 * hh + 1] *= alpha;
            }
        }
        __syncwarp();   // P region is warp-local: order STS before LDSM

        // ---- O += P V ----
#pragma unroll
        for (int ks = 0; ks < 8; ks++) {
            uint32_t pf[4], vf[8][2];
            ldsm4(pf[0], pf[1], pf[2], pf[3],
                  puB + (uint32_t)(warp * 16 * APS + ks * 8 + offP) * 4u);
#pragma unroll
            for (int ntp = 0; ntp < 4; ntp++)
                ldsm4(vf[2 * ntp][0], vf[2 * ntp][1],
                      vf[2 * ntp + 1][0], vf[2 * ntp + 1][1],
                      vtB + (uint32_t)(ntp * 16 * AVS + ks * 8 + offV) * 4u);
#pragma unroll
            for (int nt = 0; nt < 8; nt++)
                mma_tf32(oacc[nt], pf, vf[nt]);
        }
    }

    // ---- epilogue: normalize, write tf32 bits to [B,S,D] ----
    const float rinv0 = 1.0f / lrun[0];
    const float rinv1 = 1.0f / lrun[1];
    const int b = bh >> 4, h = bh & 15;
    const int row0 = q0 + qr;
#pragma unroll
    for (int nt = 0; nt < 8; nt++) {
        const int dh = nt * 8 + 2 * c;
        uint2 v0 = make_uint2(f2tf32(oacc[nt][0] * rinv0), f2tf32(oacc[nt][1] * rinv0));
        uint2 v1 = make_uint2(f2tf32(oacc[nt][2] * rinv1), f2tf32(oacc[nt][3] * rinv1));
        *(uint2*)&O[(b * SEQ + row0) * DMODEL + h * HDIM + dh] = v0;
        *(uint2*)&O[(b * SEQ + row0 + 8) * DMODEL + h * HDIM + dh] = v1;
    }
}

// ---------------------------------------------------------------------------
extern "C" void kernel_launch(void* const* d_in, const int* in_sizes, int n_in,
                              void* d_out, int out_size)
{
    const float* x  = (const float*)d_in[0];
    const float* wq = (const float*)d_in[1];
    const float* wk = (const float*)d_in[2];
    const float* wv = (const float*)d_in[3];
    const float* wo = (const float*)d_in[4];
    float* out = (float*)d_out;

    uint32_t *px, *pwq, *pwk, *pwv, *pwo, *pq, *pk, *pv, *pao;
    cudaGetSymbolAddress((void**)&px,  g_x);
    cudaGetSymbolAddress((void**)&pwq, g_wq);
    cudaGetSymbolAddress((void**)&pwk, g_wk);
    cudaGetSymbolAddress((void**)&pwv, g_wv);
    cudaGetSymbolAddress((void**)&pwo, g_wo);
    cudaGetSymbolAddress((void**)&pq,  g_q);
    cudaGetSymbolAddress((void**)&pk,  g_k);
    cudaGetSymbolAddress((void**)&pv,  g_v);
    cudaGetSymbolAddress((void**)&pao, g_ao);

    cudaFuncSetAttribute(gemm_qkv_kernel, cudaFuncAttributeMaxDynamicSharedMemorySize,
                         GEMM_SMEM_U32 * (int)sizeof(uint32_t));
    cudaFuncSetAttribute(gemm_o_kernel, cudaFuncAttributeMaxDynamicSharedMemorySize,
                         GEMM_SMEM_U32 * (int)sizeof(uint32_t));
    cudaFuncSetAttribute(attn_pipe_kernel, cudaFuncAttributeMaxDynamicSharedMemorySize,
                         ATT_SMEM_U32 * (int)sizeof(uint32_t));

    // fp32 -> tf32-bits conversions
    const int nx4 = MROWS * DMODEL / 4;
    const int nw4 = DMODEL * DMODEL / 4;
    cvt_tf32_kernel<<<nx4 / 256, 256>>>((const float4*)x,  (uint4*)px,  nx4);
    cvt_tf32_kernel<<<nw4 / 256, 256>>>((const float4*)wq, (uint4*)pwq, nw4);
    cvt_tf32_kernel<<<nw4 / 256, 256>>>((const float4*)wk, (uint4*)pwk, nw4);
    cvt_tf32_kernel<<<nw4 / 256, 256>>>((const float4*)wv, (uint4*)pwv, nw4);
    cvt_tf32_kernel<<<nw4 / 256, 256>>>((const float4*)wo, (uint4*)pwo, nw4);

    const size_t gsm = GEMM_SMEM_U32 * sizeof(uint32_t);
    const dim3 qkv_grid(DMODEL / 128, MROWS / 128, 3);   // (8, 64, 3)
    gemm_qkv_kernel<<<qkv_grid, 256, gsm>>>(px, pwq, pwk, pwv, pq, pk, pv);

    const dim3 agrid(SEQ / 128, BATCH * NHEADS);         // (16, 64)
    attn_pipe_kernel<<<agrid, 256, ATT_SMEM_U32 * sizeof(uint32_t)>>>(pq, pk, pv, pao);

    const dim3 ogrid(DMODEL / 128, MROWS / 128);         // (8, 64)
    gemm_o_kernel<<<ogrid, 256, gsm>>>(pao, pwo, out);
}

// round 10
// speedup vs baseline: 1.8068x; 1.0190x over previous
#include <cuda_runtime.h>
#include <cuda_bf16.h>
#include <cstdint>

#define BATCH 4
#define SEQ 2048
#define DMODEL 1024
#define NHEADS 16
#define HDIM 64
#define MROWS (BATCH * SEQ)      // 8192

// Scratch (device globals; all matmul operands live as tf32 bit patterns)
__device__ uint32_t g_x [MROWS * DMODEL];               // x, tf32 bits
__device__ uint32_t g_wq[DMODEL * DMODEL];
__device__ uint32_t g_wk[DMODEL * DMODEL];
__device__ uint32_t g_wv[DMODEL * DMODEL];
__device__ uint32_t g_wo[DMODEL * DMODEL];
__device__ uint32_t g_q [BATCH * NHEADS * SEQ * HDIM];  // [B,H,S,Dh] tf32 bits
__device__ uint32_t g_k [BATCH * NHEADS * SEQ * HDIM];  // [B,H,S,Dh]
__device__ uint32_t g_v [BATCH * NHEADS * HDIM * SEQ];  // [B,H,Dh,S]  (transposed)
__device__ uint32_t g_ao[BATCH * SEQ * DMODEL];         // [B,S,D] tf32 bits

__device__ __forceinline__ uint32_t f2tf32(float x) {
    uint32_t r;
    asm("cvt.rna.tf32.f32 %0, %1;" : "=r"(r) : "f"(x));
    return r;
}
__device__ __forceinline__ float fexp2(float x) {
    float y;
    asm("ex2.approx.ftz.f32 %0, %1;" : "=f"(y) : "f"(x));
    return y;
}
__device__ __forceinline__ void mma_tf32(float* c, const uint32_t* a, const uint32_t* b) {
    asm volatile(
        "mma.sync.aligned.m16n8k8.row.col.f32.tf32.tf32.f32 "
        "{%0,%1,%2,%3}, {%4,%5,%6,%7}, {%8,%9}, {%0,%1,%2,%3};"
        : "+f"(c[0]), "+f"(c[1]), "+f"(c[2]), "+f"(c[3])
        : "r"(a[0]), "r"(a[1]), "r"(a[2]), "r"(a[3]), "r"(b[0]), "r"(b[1]));
}
__device__ __forceinline__ void ldsm4(uint32_t& r0, uint32_t& r1,
                                      uint32_t& r2, uint32_t& r3, uint32_t addr) {
    asm volatile("ldmatrix.sync.aligned.m8n8.x4.shared.b16 {%0,%1,%2,%3}, [%4];"
                 : "=r"(r0), "=r"(r1), "=r"(r2), "=r"(r3) : "r"(addr));
}
__device__ __forceinline__ uint32_t smem_u32(const void* p) {
    return (uint32_t)__cvta_generic_to_shared(p);
}
__device__ __forceinline__ void cp16(uint32_t dst, const void* src) {
    asm volatile("cp.async.cg.shared.global [%0], [%1], 16;" :: "r"(dst), "l"(src));
}
__device__ __forceinline__ void cp_commit() { asm volatile("cp.async.commit_group;"); }
template<int N> __device__ __forceinline__ void cp_wait() {
    asm volatile("cp.async.wait_group %0;" :: "n"(N));
}

// ---------------------------------------------------------------------------
// fp32 -> tf32-bits elementwise convert, single fused launch over all buffers
// x: 2M float4, then 4 weights x 256K float4 each
// ---------------------------------------------------------------------------
#define NX4 (MROWS * DMODEL / 4)        // 2097152
#define NW4 (DMODEL * DMODEL / 4)       // 262144
__global__ __launch_bounds__(256) void cvt_all_kernel(
    const float4* __restrict__ x,
    const float4* __restrict__ wq, const float4* __restrict__ wk,
    const float4* __restrict__ wv, const float4* __restrict__ wo,
    uint4* __restrict__ ox,
    uint4* __restrict__ oq, uint4* __restrict__ ok,
    uint4* __restrict__ ov, uint4* __restrict__ oo)
{
    const int i = blockIdx.x * blockDim.x + threadIdx.x;
    const float4* src;
    uint4* dst;
    int off;
    if (i < NX4) { src = x; dst = ox; off = i; }
    else {
        const int k = i - NX4;
        const int w = k >> 18;          // /NW4
        off = k & (NW4 - 1);
        src = (w == 0) ? wq : (w == 1) ? wk : (w == 2) ? wv : wo;
        dst = (w == 0) ? oq : (w == 1) ? ok : (w == 2) ? ov : oo;
    }
    float4 v = src[off];
    dst[off] = make_uint4(f2tf32(v.x), f2tf32(v.y), f2tf32(v.z), f2tf32(v.w));
}

// ---------------------------------------------------------------------------
// Pipelined tf32 GEMM core, ldmatrix fragment loads.
// C = A[M,K] * B[N,K]^T, 128x128 block, BK=32, 3-stage cp.async.
// Smem [m][k] stride 36 (ldmatrix 4-row phases hit banks 0-15/16-31: c-free).
// ---------------------------------------------------------------------------
#define GKS 36
#define GEMM_SMEM_U32 (2 * 3 * 128 * GKS)   // 27648 u32 = 110592 B

struct GemmAcc { float a[4][4][4]; };

__device__ __forceinline__ void gemm_core(
    const uint32_t* __restrict__ A, const uint32_t* __restrict__ Bw,
    uint32_t* As, uint32_t* Bs, int bm, int bn, GemmAcc& G)
{
    const int tid  = threadIdx.x;
    const int warp = tid >> 5;
    const int lane = tid & 31;
    const int wm = warp >> 2;
    const int wn = warp & 3;

    // ldmatrix lane offsets (in 32-bit words)
    const int g  = lane >> 3;
    const int ri = lane & 7;
    const int offA = ((g & 1) * 8 + ri) * GKS + (g >> 1) * 4;  // A: m-rows, k-chunks
    const int offB = ((g >> 1) * 8 + ri) * GKS + (g & 1) * 4;  // B: n-rows, k-chunks

    // loader: 8 lanes per row (8x16B = 128B = 32 words), 4 rows per thread
    const int lch = tid & 7;
    const int lrw = tid >> 3;           // 0..31; rows lrw + 32j
    const uint32_t* Agl = A  + (bm + lrw) * DMODEL + lch * 4;
    const uint32_t* Bgl = Bw + (bn + lrw) * DMODEL + lch * 4;
    const uint32_t aB = smem_u32(As);
    const uint32_t bB = smem_u32(Bs);
    uint32_t dOff[4];
#pragma unroll
    for (int j = 0; j < 4; j++)
        dOff[j] = (uint32_t)(((lrw + 32 * j) * GKS + lch * 4)) * 4u;

    auto issue = [&](int s) {
        const uint32_t sb = (uint32_t)((s % 3) * 128 * GKS) * 4u;
        const int k0 = s << 5;
#pragma unroll
        for (int j = 0; j < 4; j++) {
            cp16(aB + sb + dOff[j], Agl + 32 * j * DMODEL + k0);
            cp16(bB + sb + dOff[j], Bgl + 32 * j * DMODEL + k0);
        }
    };

    issue(0); cp_commit();
    issue(1); cp_commit();

#pragma unroll
    for (int i = 0; i < 4; i++)
#pragma unroll
        for (int j = 0; j < 4; j++)
#pragma unroll
            for (int q = 0; q < 4; q++) G.a[i][j][q] = 0.0f;

    for (int t = 0; t < 32; t++) {
        cp_wait<1>();
        __syncthreads();
        if (t + 2 < 32) issue(t + 2);
        cp_commit();

        const uint32_t tb = (uint32_t)((t % 3) * 128 * GKS) * 4u;
#pragma unroll
        for (int ks = 0; ks < 32; ks += 8) {
            uint32_t af[4][4], bf[4][2];
#pragma unroll
            for (int mt = 0; mt < 4; mt++)
                ldsm4(af[mt][0], af[mt][1], af[mt][2], af[mt][3],
                      aB + tb + (uint32_t)(((wm * 64 + mt * 16) * GKS) + ks + offA) * 4u);
#pragma unroll
            for (int ntp = 0; ntp < 2; ntp++)
                ldsm4(bf[2 * ntp][0], bf[2 * ntp][1], bf[2 * ntp + 1][0], bf[2 * ntp + 1][1],
                      bB + tb + (uint32_t)(((wn * 32 + ntp * 16) * GKS) + ks + offB) * 4u);
#pragma unroll
            for (int mt = 0; mt < 4; mt++)
#pragma unroll
                for (int nt = 0; nt < 4; nt++)
                    mma_tf32(G.a[mt][nt], af[mt], bf[nt]);
        }
    }
}

// Fused QKV projection: gridDim.z selects weight/output; scatter tf32 bits.
// z==2 (V) scatters TRANSPOSED to [B,H,Dh,S].
__global__ __launch_bounds__(256, 2) void gemm_qkv_kernel(
    const uint32_t* __restrict__ X,
    const uint32_t* __restrict__ Wq, const uint32_t* __restrict__ Wk,
    const uint32_t* __restrict__ Wv,
    uint32_t* __restrict__ Oq, uint32_t* __restrict__ Ok,
    uint32_t* __restrict__ Ov)
{
    extern __shared__ uint32_t gsm[];
    const int zi = blockIdx.z;
    const uint32_t* W = (zi == 0) ? Wq : (zi == 1) ? Wk : Wv;
    uint32_t* C = (zi == 0) ? Oq : (zi == 1) ? Ok : Ov;

    const int bm = blockIdx.y << 7;
    const int bn = blockIdx.x << 7;
    GemmAcc G;
    gemm_core(X, W, gsm, gsm + 3 * 128 * GKS, bm, bn, G);

    const int lane = threadIdx.x & 31;
    const int warp = threadIdx.x >> 5;
    const int r = lane >> 2, c = lane & 3;
    const int wm = warp >> 2, wn = warp & 3;
#pragma unroll
    for (int mt = 0; mt < 4; mt++) {
        const int m0 = bm + wm * 64 + mt * 16 + r;
#pragma unroll
        for (int nt = 0; nt < 4; nt++) {
            const int n = bn + wn * 32 + nt * 8 + c * 2;
            const int h = n >> 6;
            const int dh = n & 63;
#pragma unroll
            for (int half = 0; half < 2; half++) {
                const int m = m0 + half * 8;
                const int b = m >> 11;
                const int s = m & (SEQ - 1);
                const uint32_t v0 = f2tf32(G.a[mt][nt][half * 2]);
                const uint32_t v1 = f2tf32(G.a[mt][nt][half * 2 + 1]);
                if (zi == 2) {
                    const int base = ((b * NHEADS + h) * HDIM + dh) * SEQ + s;
                    C[base] = v0;
                    C[base + SEQ] = v1;
                } else {
                    *(uint2*)&C[((b * NHEADS + h) * SEQ + s) * HDIM + dh] =
                        make_uint2(v0, v1);
                }
            }
        }
    }
}

// O projection: fp32 row-major output.
__global__ __launch_bounds__(256, 2) void gemm_o_kernel(
    const uint32_t* __restrict__ A, const uint32_t* __restrict__ W,
    float* __restrict__ C)
{
    extern __shared__ uint32_t gsm[];
    const int bm = blockIdx.y << 7;
    const int bn = blockIdx.x << 7;
    GemmAcc G;
    gemm_core(A, W, gsm, gsm + 3 * 128 * GKS, bm, bn, G);

    const int lane = threadIdx.x & 31;
    const int warp = threadIdx.x >> 5;
    const int r = lane >> 2, c = lane & 3;
    const int wm = warp >> 2, wn = warp & 3;
#pragma unroll
    for (int mt = 0; mt < 4; mt++) {
        const int m0 = bm + wm * 64 + mt * 16 + r;
#pragma unroll
        for (int nt = 0; nt < 4; nt++) {
            const int n = bn + wn * 32 + nt * 8 + c * 2;
#pragma unroll
            for (int half = 0; half < 2; half++) {
                const int m = m0 + half * 8;
                float2 v = make_float2(G.a[mt][nt][half * 2],
                                       G.a[mt][nt][half * 2 + 1]);
                *(float2*)&C[m * DMODEL + n] = v;
            }
        }
    }
}

// ---------------------------------------------------------------------------
// Pipelined tf32 flash attention (causal), ldmatrix fragment loads.
// 256 threads = 8 warps; q-tile 128, kv-tile 64, double-buffered cp.async.
// K smem [kseq][dh]; V smem [dh][kseq] (transposed g_v); P smem [q][kseq].
// ---------------------------------------------------------------------------
#define AKS 68
#define AVS 68
#define APS 68
#define ATT_SMEM_U32 (2 * 64 * AKS + 2 * 64 * AVS + 128 * APS)
#define QSCALE (0.125f * 1.4426950408889634f)

__global__ __launch_bounds__(256, 2) void attn_pipe_kernel(
    const uint32_t* __restrict__ Q, const uint32_t* __restrict__ K,
    const uint32_t* __restrict__ V, uint32_t* __restrict__ O)
{
    extern __shared__ uint32_t smu[];
    uint32_t* Ks = smu;                               // [2][64][AKS]  rows=kseq
    uint32_t* Vs = smu + 2 * 64 * AKS;                // [2][64][AVS]  rows=dh
    uint32_t* Pu = smu + 2 * 64 * AKS + 2 * 64 * AVS; // [128][APS]    rows=q

    const int tid  = threadIdx.x;
    const int warp = tid >> 5;
    const int lane = tid & 31;
    const int r = lane >> 2;
    const int c = lane & 3;
    const int g  = lane >> 3;
    const int ri = lane & 7;

    const int offK = ((g >> 1) * 8 + ri) * AKS + (g & 1) * 4;
    const int offV = ((g >> 1) * 8 + ri) * AVS + (g & 1) * 4;
    const int offP = ((g & 1) * 8 + ri) * APS + (g >> 1) * 4;

    const int bh = blockIdx.y;
    const int QT = gridDim.x - 1 - blockIdx.x;    // longest first
    const int q0 = QT << 7;
    const uint32_t* Qb = Q + bh * (SEQ * HDIM);
    const uint32_t* Kb = K + bh * (SEQ * HDIM);
    const uint32_t* Vb = V + bh * (HDIM * SEQ);   // [Dh][S]

    {
        const int qrow = tid >> 1;
        const int qcol = (tid & 1) << 5;
#pragma unroll
        for (int cc = 0; cc < 32; cc += 4)
            *(uint4*)&Pu[qrow * APS + qcol + cc] =
                *(const uint4*)&Qb[(q0 + qrow) * HDIM + qcol + cc];
    }
    __syncthreads();

    const int qr = warp * 16 + r;
    uint32_t qf[8][4];
#pragma unroll
    for (int ks = 0; ks < 8; ks++) {
        const int d = ks * 8 + c;
        qf[ks][0] = f2tf32(QSCALE * __uint_as_float(Pu[qr * APS + d]));
        qf[ks][1] = f2tf32(QSCALE * __uint_as_float(Pu[(qr + 8) * APS + d]));
        qf[ks][2] = f2tf32(QSCALE * __uint_as_float(Pu[qr * APS + d + 4]));
        qf[ks][3] = f2tf32(QSCALE * __uint_as_float(Pu[(qr + 8) * APS + d + 4]));
    }

    const int ch  = tid & 15;
    const int lr0 = tid >> 4;
    const uint32_t ksB = smem_u32(Ks);
    const uint32_t vsB = smem_u32(Vs);
    const uint32_t puB = smem_u32(Pu);

    auto issue_kv = [&](int t) {
        const int buf = t & 1;
        const int k0 = t << 6;
#pragma unroll
        for (int j = 0; j < 4; j++) {
            const int row = lr0 + 16 * j;
            cp16(ksB + ((buf * 64 + row) * AKS + ch * 4) * 4u,
                 Kb + (k0 + row) * HDIM + ch * 4);
            cp16(vsB + ((buf * 64 + row) * AVS + ch * 4) * 4u,
                 Vb + row * SEQ + k0 + ch * 4);
        }
    };

    issue_kv(0); cp_commit();

    float oacc[8][4];
#pragma unroll
    for (int nt = 0; nt < 8; nt++)
#pragma unroll
        for (int j = 0; j < 4; j++) oacc[nt][j] = 0.0f;
    float mrun[2] = {-1e30f, -1e30f};
    float lrun[2] = {0.0f, 0.0f};

    const int T = 2 * QT + 1;
    for (int t = 0; t <= T; t++) {
        cp_wait<0>();
        __syncthreads();
        if (t < T) issue_kv(t + 1);
        cp_commit();

        const uint32_t ktB = ksB + (uint32_t)((t & 1) * 64 * AKS) * 4u;
        const uint32_t vtB = vsB + (uint32_t)((t & 1) * 64 * AVS) * 4u;

        float sacc[8][4];
#pragma unroll
        for (int nt = 0; nt < 8; nt++)
#pragma unroll
            for (int j = 0; j < 4; j++) sacc[nt][j] = 0.0f;
#pragma unroll
        for (int ks = 0; ks < 8; ks++) {
            uint32_t kf[8][2];
#pragma unroll
            for (int ntp = 0; ntp < 4; ntp++)
                ldsm4(kf[2 * ntp][0], kf[2 * ntp][1],
                      kf[2 * ntp + 1][0], kf[2 * ntp + 1][1],
                      ktB + (uint32_t)(ntp * 16 * AKS + ks * 8 + offK) * 4u);
#pragma unroll
            for (int nt = 0; nt < 8; nt++)
                mma_tf32(sacc[nt], qf[ks], kf[nt]);
        }

        if (t >= 2 * QT) {
            const int kbase = t << 6;
#pragma unroll
            for (int nt = 0; nt < 8; nt++)
#pragma unroll
                for (int j = 0; j < 4; j++) {
                    const int kg = kbase + nt * 8 + 2 * c + (j & 1);
                    const int qg = q0 + warp * 16 + r + (j >> 1) * 8;
                    if (kg > qg) sacc[nt][j] = -1e30f;
                }
        }

#pragma unroll
        for (int hh = 0; hh < 2; hh++) {
            float tm = -1e30f;
#pragma unroll
            for (int nt = 0; nt < 8; nt++)
                tm = fmaxf(tm, fmaxf(sacc[nt][2 * hh], sacc[nt][2 * hh + 1]));
            tm = fmaxf(tm, __shfl_xor_sync(0xffffffffu, tm, 1));
            tm = fmaxf(tm, __shfl_xor_sync(0xffffffffu, tm, 2));
            const float mnew  = fmaxf(mrun[hh], tm);
            const float alpha = fexp2(mrun[hh] - mnew);
            float ls = 0.0f;
            const int prow = (warp * 16 + r + hh * 8) * APS;
#pragma unroll
            for (int nt = 0; nt < 8; nt++) {
                const float p0 = fexp2(sacc[nt][2 * hh] - mnew);
                const float p1 = fexp2(sacc[nt][2 * hh + 1] - mnew);
                ls += p0 + p1;
                uint2 pv = make_uint2(f2tf32(p0), f2tf32(p1));
                *(uint2*)&Pu[prow + nt * 8 + 2 * c] = pv;
            }
            ls += __shfl_xor_sync(0xffffffffu, ls, 1);
            ls += __shfl_xor_sync(0xffffffffu, ls, 2);
            lrun[hh] = lrun[hh] * alpha + ls;
            mrun[hh] = mnew;
#pragma unroll
            for (int nt = 0; nt < 8; nt++) {
                oacc[nt][2 * hh]     *= alpha;
                oacc[nt][2 * hh + 1] *= alpha;
            }
        }
        __syncwarp();   // P region is warp-local: order STS before LDSM

#pragma unroll
        for (int ks = 0; ks < 8; ks++) {
            uint32_t pf[4], vf[8][2];
            ldsm4(pf[0], pf[1], pf[2], pf[3],
                  puB + (uint32_t)(warp * 16 * APS + ks * 8 + offP) * 4u);
#pragma unroll
            for (int ntp = 0; ntp < 4; ntp++)
                ldsm4(vf[2 * ntp][0], vf[2 * ntp][1],
                      vf[2 * ntp + 1][0], vf[2 * ntp + 1][1],
                      vtB + (uint32_t)(ntp * 16 * AVS + ks * 8 + offV) * 4u);
#pragma unroll
            for (int nt = 0; nt < 8; nt++)
                mma_tf32(oacc[nt], pf, vf[nt]);
        }
    }

    const float rinv0 = 1.0f / lrun[0];
    const float rinv1 = 1.0f / lrun[1];
    const int b = bh >> 4, h = bh & 15;
    const int row0 = q0 + qr;
#pragma unroll
    for (int nt = 0; nt < 8; nt++) {
        const int dh = nt * 8 + 2 * c;
        uint2 v0 = make_uint2(f2tf32(oacc[nt][0] * rinv0), f2tf32(oacc[nt][1] * rinv0));
        uint2 v1 = make_uint2(f2tf32(oacc[nt][2] * rinv1), f2tf32(oacc[nt][3] * rinv1));
        *(uint2*)&O[(b * SEQ + row0) * DMODEL + h * HDIM + dh] = v0;
        *(uint2*)&O[(b * SEQ + row0 + 8) * DMODEL + h * HDIM + dh] = v1;
    }
}

// ---------------------------------------------------------------------------
extern "C" void kernel_launch(void* const* d_in, const int* in_sizes, int n_in,
                              void* d_out, int out_size)
{
    const float* x  = (const float*)d_in[0];
    const float* wq = (const float*)d_in[1];
    const float* wk = (const float*)d_in[2];
    const float* wv = (const float*)d_in[3];
    const float* wo = (const float*)d_in[4];
    float* out = (float*)d_out;

    uint32_t *px, *pwq, *pwk, *pwv, *pwo, *pq, *pk, *pv, *pao;
    cudaGetSymbolAddress((void**)&px,  g_x);
    cudaGetSymbolAddress((void**)&pwq, g_wq);
    cudaGetSymbolAddress((void**)&pwk, g_wk);
    cudaGetSymbolAddress((void**)&pwv, g_wv);
    cudaGetSymbolAddress((void**)&pwo, g_wo);
    cudaGetSymbolAddress((void**)&pq,  g_q);
    cudaGetSymbolAddress((void**)&pk,  g_k);
    cudaGetSymbolAddress((void**)&pv,  g_v);
    cudaGetSymbolAddress((void**)&pao, g_ao);

    cudaFuncSetAttribute(gemm_qkv_kernel, cudaFuncAttributeMaxDynamicSharedMemorySize,
                         GEMM_SMEM_U32 * (int)sizeof(uint32_t));
    cudaFuncSetAttribute(gemm_o_kernel, cudaFuncAttributeMaxDynamicSharedMemorySize,
                         GEMM_SMEM_U32 * (int)sizeof(uint32_t));
    cudaFuncSetAttribute(attn_pipe_kernel, cudaFuncAttributeMaxDynamicSharedMemorySize,
                         ATT_SMEM_U32 * (int)sizeof(uint32_t));

    // fp32 -> tf32-bits conversion, one fused launch
    const int total4 = NX4 + 4 * NW4;
    cvt_all_kernel<<<total4 / 256, 256>>>(
        (const float4*)x, (const float4*)wq, (const float4*)wk,
        (const float4*)wv, (const float4*)wo,
        (uint4*)px, (uint4*)pwq, (uint4*)pwk, (uint4*)pwv, (uint4*)pwo);

    const size_t gsm = GEMM_SMEM_U32 * sizeof(uint32_t);
    const dim3 qkv_grid(DMODEL / 128, MROWS / 128, 3);   // (8, 64, 3)
    gemm_qkv_kernel<<<qkv_grid, 256, gsm>>>(px, pwq, pwk, pwv, pq, pk, pv);

    const dim3 agrid(SEQ / 128, BATCH * NHEADS);         // (16, 64)
    attn_pipe_kernel<<<agrid, 256, ATT_SMEM_U32 * sizeof(uint32_t)>>>(pq, pk, pv, pao);

    const dim3 ogrid(DMODEL / 128, MROWS / 128);         // (8, 64)
    gemm_o_kernel<<<ogrid, 256, gsm>>>(pao, pwo, out);
}

// round 11
// speedup vs baseline: 2.1564x; 1.1935x over previous
#include <cuda_runtime.h>
#include <cuda.h>
#include <cuda_bf16.h>
#include <cstdint>

#define BATCH 4
#define SEQ 2048
#define DMODEL 1024
#define NHEADS 16
#define HDIM 64
#define MROWS (BATCH * SEQ)      // 8192

// Scratch (device globals; all matmul operands live as tf32 bit patterns)
__device__ uint32_t g_x [MROWS * DMODEL];               // x, tf32 bits
__device__ uint32_t g_wq[DMODEL * DMODEL];
__device__ uint32_t g_wk[DMODEL * DMODEL];
__device__ uint32_t g_wv[DMODEL * DMODEL];
__device__ uint32_t g_wo[DMODEL * DMODEL];
__device__ uint32_t g_q [BATCH * NHEADS * SEQ * HDIM];  // [B,H,S,Dh] tf32 bits
__device__ uint32_t g_k [BATCH * NHEADS * SEQ * HDIM];  // [B,H,S,Dh]
__device__ uint32_t g_v [BATCH * NHEADS * HDIM * SEQ];  // [B,H,Dh,S]  (transposed)
__device__ uint32_t g_ao[BATCH * SEQ * DMODEL];         // [B,S,D] tf32 bits

__device__ __forceinline__ uint32_t f2tf32(float x) {
    uint32_t r;
    asm("cvt.rna.tf32.f32 %0, %1;" : "=r"(r) : "f"(x));
    return r;
}
__device__ __forceinline__ float fexp2(float x) {
    float y;
    asm("ex2.approx.ftz.f32 %0, %1;" : "=f"(y) : "f"(x));
    return y;
}
__device__ __forceinline__ void mma_tf32(float* c, const uint32_t* a, const uint32_t* b) {
    asm volatile(
        "mma.sync.aligned.m16n8k8.row.col.f32.tf32.tf32.f32 "
        "{%0,%1,%2,%3}, {%4,%5,%6,%7}, {%8,%9}, {%0,%1,%2,%3};"
        : "+f"(c[0]), "+f"(c[1]), "+f"(c[2]), "+f"(c[3])
        : "r"(a[0]), "r"(a[1]), "r"(a[2]), "r"(a[3]), "r"(b[0]), "r"(b[1]));
}
__device__ __forceinline__ void ldsm4(uint32_t& r0, uint32_t& r1,
                                      uint32_t& r2, uint32_t& r3, uint32_t addr) {
    asm volatile("ldmatrix.sync.aligned.m8n8.x4.shared.b16 {%0,%1,%2,%3}, [%4];"
                 : "=r"(r0), "=r"(r1), "=r"(r2), "=r"(r3) : "r"(addr));
}
__device__ __forceinline__ uint32_t smem_u32(const void* p) {
    return (uint32_t)__cvta_generic_to_shared(p);
}
__device__ __forceinline__ void cp16(uint32_t dst, const void* src) {
    asm volatile("cp.async.cg.shared.global [%0], [%1], 16;" :: "r"(dst), "l"(src));
}
__device__ __forceinline__ void cp_commit() { asm volatile("cp.async.commit_group;"); }
template<int N> __device__ __forceinline__ void cp_wait() {
    asm volatile("cp.async.wait_group %0;" :: "n"(N));
}
// ---- TMA / mbarrier helpers (sm_90-base PTX) ----
__device__ __forceinline__ void tma2d(uint32_t smem, const CUtensorMap* tmap,
                                      int x, int y, uint32_t mbar) {
    asm volatile(
        "cp.async.bulk.tensor.2d.shared::cta.global.tile.mbarrier::complete_tx::bytes "
        "[%0], [%1, {%2, %3}], [%4];"
        :: "r"(smem), "l"(tmap), "r"(x), "r"(y), "r"(mbar) : "memory");
}
__device__ __forceinline__ void mbar_init(uint32_t mbar, uint32_t cnt) {
    asm volatile("mbarrier.init.shared.b64 [%0], %1;" :: "r"(mbar), "r"(cnt) : "memory");
}
__device__ __forceinline__ void mbar_expect_tx(uint32_t mbar, uint32_t bytes) {
    asm volatile("mbarrier.arrive.expect_tx.shared.b64 _, [%0], %1;"
                 :: "r"(mbar), "r"(bytes) : "memory");
}
__device__ __forceinline__ void mbar_arrive(uint32_t mbar) {
    asm volatile("mbarrier.arrive.shared.b64 _, [%0];" :: "r"(mbar) : "memory");
}
__device__ __forceinline__ void mbar_wait(uint32_t mbar, uint32_t phase) {
    uint32_t ok = 0;
    while (!ok) {
        asm volatile("{\n\t.reg .pred p;\n\t"
                     "mbarrier.try_wait.parity.acquire.cta.shared::cta.b64 p, [%1], %2;\n\t"
                     "selp.b32 %0, 1, 0, p;\n\t}"
                     : "=r"(ok) : "r"(mbar), "r"(phase) : "memory");
    }
}

// ---------------------------------------------------------------------------
// fp32 -> tf32-bits elementwise convert, single fused launch
// ---------------------------------------------------------------------------
#define NX4 (MROWS * DMODEL / 4)
#define NW4 (DMODEL * DMODEL / 4)
__global__ __launch_bounds__(256) void cvt_all_kernel(
    const float4* __restrict__ x,
    const float4* __restrict__ wq, const float4* __restrict__ wk,
    const float4* __restrict__ wv, const float4* __restrict__ wo,
    uint4* __restrict__ ox,
    uint4* __restrict__ oq, uint4* __restrict__ ok,
    uint4* __restrict__ ov, uint4* __restrict__ oo)
{
    const int i = blockIdx.x * blockDim.x + threadIdx.x;
    const float4* src;
    uint4* dst;
    int off;
    if (i < NX4) { src = x; dst = ox; off = i; }
    else {
        const int k = i - NX4;
        const int w = k >> 18;
        off = k & (NW4 - 1);
        src = (w == 0) ? wq : (w == 1) ? wk : (w == 2) ? wv : wo;
        dst = (w == 0) ? oq : (w == 1) ? ok : (w == 2) ? ov : oo;
    }
    float4 v = src[off];
    dst[off] = make_uint4(f2tf32(v.x), f2tf32(v.y), f2tf32(v.z), f2tf32(v.w));
}

// ---------------------------------------------------------------------------
// TMA-fed tf32 GEMM: C = A[M,K] * B[N,K]^T, 128x128 CTA tile, BK=32,
// 3-stage mbarrier pipeline, SW128 smem (128B rows), ldmatrix + XOR swizzle.
// ---------------------------------------------------------------------------
#define STAGEB 16384                    // 128 rows x 128 B per operand
#define TG_SMEM (1024 + 6 * STAGEB)     // 99328 B

struct GemmAcc { float a[4][4][4]; };

__device__ __forceinline__ void tma_gemm_core(
    const CUtensorMap* tA, const CUtensorMap* tB, int bm, int bn, GemmAcc& G)
{
    extern __shared__ uint32_t gsm[];
    const uint32_t sb  = smem_u32(gsm);
    const uint32_t stA = sb + 1024;
    const uint32_t stB = sb + 1024 + 3 * STAGEB;
    const int tid  = threadIdx.x;
    const int warp = tid >> 5;
    const int lane = tid & 31;
    const int wm = warp >> 2, wn = warp & 3;
    const int g  = lane >> 3, ri = lane & 7;

    // barriers: full[s] at sb+64+16s (count 1 + tx), empty[s] at sb+160+16s (count 256)
    if (tid == 0) {
#pragma unroll
        for (int s = 0; s < 3; s++) {
            mbar_init(sb + 64 + 16 * s, 1);
            mbar_init(sb + 160 + 16 * s, 256);
        }
    }
    __syncthreads();
    if (tid == 0) {
#pragma unroll
        for (int s = 0; s < 3; s++) {
            mbar_expect_tx(sb + 64 + 16 * s, 2 * STAGEB);
            tma2d(stA + s * STAGEB, tA, s * 32, bm, sb + 64 + 16 * s);
            tma2d(stB + s * STAGEB, tB, s * 32, bn, sb + 64 + 16 * s);
        }
    }

    // per-lane ldmatrix row offsets (bytes) into a 16KB stage
    uint32_t aRow[4], bRow[2];
#pragma unroll
    for (int mt = 0; mt < 4; mt++)
        aRow[mt] = (uint32_t)((wm * 64 + mt * 16 + (g & 1) * 8 + ri) * 128);
#pragma unroll
    for (int np = 0; np < 2; np++)
        bRow[np] = (uint32_t)((wn * 32 + np * 16 + (g >> 1) * 8 + ri) * 128);
    const int asel = g >> 1, bsel = g & 1;

#pragma unroll
    for (int i = 0; i < 4; i++)
#pragma unroll
        for (int j = 0; j < 4; j++)
#pragma unroll
            for (int q = 0; q < 4; q++) G.a[i][j][q] = 0.0f;

    for (int t = 0; t < 32; t++) {
        const int buf = t % 3;
        const uint32_t sA = stA + (uint32_t)buf * STAGEB;
        const uint32_t sBs = stB + (uint32_t)buf * STAGEB;
        mbar_wait(sb + 64 + 16 * buf, (uint32_t)((t / 3) & 1));

#pragma unroll
        for (int ks = 0; ks < 4; ks++) {
            const uint32_t aCh = (uint32_t)(((ks * 2 + asel) ^ ri) * 16);
            const uint32_t bCh = (uint32_t)(((ks * 2 + bsel) ^ ri) * 16);
            uint32_t af[4][4], bf[4][2];
#pragma unroll
            for (int mt = 0; mt < 4; mt++)
                ldsm4(af[mt][0], af[mt][1], af[mt][2], af[mt][3],
                      sA + aRow[mt] + aCh);
#pragma unroll
            for (int np = 0; np < 2; np++)
                ldsm4(bf[2 * np][0], bf[2 * np][1], bf[2 * np + 1][0], bf[2 * np + 1][1],
                      sBs + bRow[np] + bCh);
#pragma unroll
            for (int mt = 0; mt < 4; mt++)
#pragma unroll
                for (int nt = 0; nt < 4; nt++)
                    mma_tf32(G.a[mt][nt], af[mt], bf[nt]);
        }

        mbar_arrive(sb + 160 + 16 * buf);
        if (t + 3 < 32 && tid == 0) {
            mbar_wait(sb + 160 + 16 * buf, (uint32_t)((t / 3) & 1));
            mbar_expect_tx(sb + 64 + 16 * buf, 2 * STAGEB);
            tma2d(sA,  tA, (t + 3) * 32, bm, sb + 64 + 16 * buf);
            tma2d(sBs, tB, (t + 3) * 32, bn, sb + 64 + 16 * buf);
        }
    }
}

// Fused QKV projection; z selects weight/output. z==2 (V) scatters transposed.
__global__ __launch_bounds__(256, 2) void gemm_qkv_tma(
    const __grid_constant__ CUtensorMap tX,
    const __grid_constant__ CUtensorMap tWq,
    const __grid_constant__ CUtensorMap tWk,
    const __grid_constant__ CUtensorMap tWv,
    uint32_t* __restrict__ Oq, uint32_t* __restrict__ Ok,
    uint32_t* __restrict__ Ov)
{
    const int zi = blockIdx.z;
    const CUtensorMap* tW = (zi == 0) ? &tWq : (zi == 1) ? &tWk : &tWv;
    uint32_t* C = (zi == 0) ? Oq : (zi == 1) ? Ok : Ov;

    const int bm = blockIdx.y << 7;
    const int bn = blockIdx.x << 7;
    GemmAcc G;
    tma_gemm_core(&tX, tW, bm, bn, G);

    const int lane = threadIdx.x & 31;
    const int warp = threadIdx.x >> 5;
    const int r = lane >> 2, c = lane & 3;
    const int wm = warp >> 2, wn = warp & 3;
#pragma unroll
    for (int mt = 0; mt < 4; mt++) {
        const int m0 = bm + wm * 64 + mt * 16 + r;
#pragma unroll
        for (int nt = 0; nt < 4; nt++) {
            const int n = bn + wn * 32 + nt * 8 + c * 2;
            const int h = n >> 6;
            const int dh = n & 63;
#pragma unroll
            for (int half = 0; half < 2; half++) {
                const int m = m0 + half * 8;
                const int b = m >> 11;
                const int s = m & (SEQ - 1);
                const uint32_t v0 = f2tf32(G.a[mt][nt][half * 2]);
                const uint32_t v1 = f2tf32(G.a[mt][nt][half * 2 + 1]);
                if (zi == 2) {
                    const int base = ((b * NHEADS + h) * HDIM + dh) * SEQ + s;
                    C[base] = v0;
                    C[base + SEQ] = v1;
                } else {
                    *(uint2*)&C[((b * NHEADS + h) * SEQ + s) * HDIM + dh] =
                        make_uint2(v0, v1);
                }
            }
        }
    }
}

// O projection: fp32 row-major output.
__global__ __launch_bounds__(256, 2) void gemm_o_tma(
    const __grid_constant__ CUtensorMap tA,
    const __grid_constant__ CUtensorMap tW,
    float* __restrict__ C)
{
    const int bm = blockIdx.y << 7;
    const int bn = blockIdx.x << 7;
    GemmAcc G;
    tma_gemm_core(&tA, &tW, bm, bn, G);

    const int lane = threadIdx.x & 31;
    const int warp = threadIdx.x >> 5;
    const int r = lane >> 2, c = lane & 3;
    const int wm = warp >> 2, wn = warp & 3;
#pragma unroll
    for (int mt = 0; mt < 4; mt++) {
        const int m0 = bm + wm * 64 + mt * 16 + r;
#pragma unroll
        for (int nt = 0; nt < 4; nt++) {
            const int n = bn + wn * 32 + nt * 8 + c * 2;
#pragma unroll
            for (int half = 0; half < 2; half++) {
                const int m = m0 + half * 8;
                float2 v = make_float2(G.a[mt][nt][half * 2],
                                       G.a[mt][nt][half * 2 + 1]);
                *(float2*)&C[m * DMODEL + n] = v;
            }
        }
    }
}

// ---------------------------------------------------------------------------
// Pipelined tf32 flash attention (causal), ldmatrix fragment loads (R9).
// ---------------------------------------------------------------------------
#define AKS 68
#define AVS 68
#define APS 68
#define ATT_SMEM_U32 (2 * 64 * AKS + 2 * 64 * AVS + 128 * APS)
#define QSCALE (0.125f * 1.4426950408889634f)

__global__ __launch_bounds__(256, 2) void attn_pipe_kernel(
    const uint32_t* __restrict__ Q, const uint32_t* __restrict__ K,
    const uint32_t* __restrict__ V, uint32_t* __restrict__ O)
{
    extern __shared__ uint32_t smu[];
    uint32_t* Ks = smu;
    uint32_t* Vs = smu + 2 * 64 * AKS;
    uint32_t* Pu = smu + 2 * 64 * AKS + 2 * 64 * AVS;

    const int tid  = threadIdx.x;
    const int warp = tid >> 5;
    const int lane = tid & 31;
    const int r = lane >> 2;
    const int c = lane & 3;
    const int g  = lane >> 3;
    const int ri = lane & 7;

    const int offK = ((g >> 1) * 8 + ri) * AKS + (g & 1) * 4;
    const int offV = ((g >> 1) * 8 + ri) * AVS + (g & 1) * 4;
    const int offP = ((g & 1) * 8 + ri) * APS + (g >> 1) * 4;

    const int bh = blockIdx.y;
    const int QT = gridDim.x - 1 - blockIdx.x;
    const int q0 = QT << 7;
    const uint32_t* Qb = Q + bh * (SEQ * HDIM);
    const uint32_t* Kb = K + bh * (SEQ * HDIM);
    const uint32_t* Vb = V + bh * (HDIM * SEQ);

    {
        const int qrow = tid >> 1;
        const int qcol = (tid & 1) << 5;
#pragma unroll
        for (int cc = 0; cc < 32; cc += 4)
            *(uint4*)&Pu[qrow * APS + qcol + cc] =
                *(const uint4*)&Qb[(q0 + qrow) * HDIM + qcol + cc];
    }
    __syncthreads();

    const int qr = warp * 16 + r;
    uint32_t qf[8][4];
#pragma unroll
    for (int ks = 0; ks < 8; ks++) {
        const int d = ks * 8 + c;
        qf[ks][0] = f2tf32(QSCALE * __uint_as_float(Pu[qr * APS + d]));
        qf[ks][1] = f2tf32(QSCALE * __uint_as_float(Pu[(qr + 8) * APS + d]));
        qf[ks][2] = f2tf32(QSCALE * __uint_as_float(Pu[qr * APS + d + 4]));
        qf[ks][3] = f2tf32(QSCALE * __uint_as_float(Pu[(qr + 8) * APS + d + 4]));
    }

    const int ch  = tid & 15;
    const int lr0 = tid >> 4;
    const uint32_t ksB = smem_u32(Ks);
    const uint32_t vsB = smem_u32(Vs);
    const uint32_t puB = smem_u32(Pu);

    auto issue_kv = [&](int t) {
        const int buf = t & 1;
        const int k0 = t << 6;
#pragma unroll
        for (int j = 0; j < 4; j++) {
            const int row = lr0 + 16 * j;
            cp16(ksB + ((buf * 64 + row) * AKS + ch * 4) * 4u,
                 Kb + (k0 + row) * HDIM + ch * 4);
            cp16(vsB + ((buf * 64 + row) * AVS + ch * 4) * 4u,
                 Vb + row * SEQ + k0 + ch * 4);
        }
    };

    issue_kv(0); cp_commit();

    float oacc[8][4];
#pragma unroll
    for (int nt = 0; nt < 8; nt++)
#pragma unroll
        for (int j = 0; j < 4; j++) oacc[nt][j] = 0.0f;
    float mrun[2] = {-1e30f, -1e30f};
    float lrun[2] = {0.0f, 0.0f};

    const int T = 2 * QT + 1;
    for (int t = 0; t <= T; t++) {
        cp_wait<0>();
        __syncthreads();
        if (t < T) issue_kv(t + 1);
        cp_commit();

        const uint32_t ktB = ksB + (uint32_t)((t & 1) * 64 * AKS) * 4u;
        const uint32_t vtB = vsB + (uint32_t)((t & 1) * 64 * AVS) * 4u;

        float sacc[8][4];
#pragma unroll
        for (int nt = 0; nt < 8; nt++)
#pragma unroll
            for (int j = 0; j < 4; j++) sacc[nt][j] = 0.0f;
#pragma unroll
        for (int ks = 0; ks < 8; ks++) {
            uint32_t kf[8][2];
#pragma unroll
            for (int ntp = 0; ntp < 4; ntp++)
                ldsm4(kf[2 * ntp][0], kf[2 * ntp][1],
                      kf[2 * ntp + 1][0], kf[2 * ntp + 1][1],
                      ktB + (uint32_t)(ntp * 16 * AKS + ks * 8 + offK) * 4u);
#pragma unroll
            for (int nt = 0; nt < 8; nt++)
                mma_tf32(sacc[nt], qf[ks], kf[nt]);
        }

        if (t >= 2 * QT) {
            const int kbase = t << 6;
#pragma unroll
            for (int nt = 0; nt < 8; nt++)
#pragma unroll
                for (int j = 0; j < 4; j++) {
                    const int kg = kbase + nt * 8 + 2 * c + (j & 1);
                    const int qg = q0 + warp * 16 + r + (j >> 1) * 8;
                    if (kg > qg) sacc[nt][j] = -1e30f;
                }
        }

#pragma unroll
        for (int hh = 0; hh < 2; hh++) {
            float tm = -1e30f;
#pragma unroll
            for (int nt = 0; nt < 8; nt++)
                tm = fmaxf(tm, fmaxf(sacc[nt][2 * hh], sacc[nt][2 * hh + 1]));
            tm = fmaxf(tm, __shfl_xor_sync(0xffffffffu, tm, 1));
            tm = fmaxf(tm, __shfl_xor_sync(0xffffffffu, tm, 2));
            const float mnew  = fmaxf(mrun[hh], tm);
            const float alpha = fexp2(mrun[hh] - mnew);
            float ls = 0.0f;
            const int prow = (warp * 16 + r + hh * 8) * APS;
#pragma unroll
            for (int nt = 0; nt < 8; nt++) {
                const float p0 = fexp2(sacc[nt][2 * hh] - mnew);
                const float p1 = fexp2(sacc[nt][2 * hh + 1] - mnew);
                ls += p0 + p1;
                uint2 pv = make_uint2(f2tf32(p0), f2tf32(p1));
                *(uint2*)&Pu[prow + nt * 8 + 2 * c] = pv;
            }
            ls += __shfl_xor_sync(0xffffffffu, ls, 1);
            ls += __shfl_xor_sync(0xffffffffu, ls, 2);
            lrun[hh] = lrun[hh] * alpha + ls;
            mrun[hh] = mnew;
#pragma unroll
            for (int nt = 0; nt < 8; nt++) {
                oacc[nt][2 * hh]     *= alpha;
                oacc[nt][2 * hh + 1] *= alpha;
            }
        }
        __syncwarp();

#pragma unroll
        for (int ks = 0; ks < 8; ks++) {
            uint32_t pf[4], vf[8][2];
            ldsm4(pf[0], pf[1], pf[2], pf[3],
                  puB + (uint32_t)(warp * 16 * APS + ks * 8 + offP) * 4u);
#pragma unroll
            for (int ntp = 0; ntp < 4; ntp++)
                ldsm4(vf[2 * ntp][0], vf[2 * ntp][1],
                      vf[2 * ntp + 1][0], vf[2 * ntp + 1][1],
                      vtB + (uint32_t)(ntp * 16 * AVS + ks * 8 + offV) * 4u);
#pragma unroll
            for (int nt = 0; nt < 8; nt++)
                mma_tf32(oacc[nt], pf, vf[nt]);
        }
    }

    const float rinv0 = 1.0f / lrun[0];
    const float rinv1 = 1.0f / lrun[1];
    const int b = bh >> 4, h = bh & 15;
    const int row0 = q0 + qr;
#pragma unroll
    for (int nt = 0; nt < 8; nt++) {
        const int dh = nt * 8 + 2 * c;
        uint2 v0 = make_uint2(f2tf32(oacc[nt][0] * rinv0), f2tf32(oacc[nt][1] * rinv0));
        uint2 v1 = make_uint2(f2tf32(oacc[nt][2] * rinv1), f2tf32(oacc[nt][3] * rinv1));
        *(uint2*)&O[(b * SEQ + row0) * DMODEL + h * HDIM + dh] = v0;
        *(uint2*)&O[(b * SEQ + row0 + 8) * DMODEL + h * HDIM + dh] = v1;
    }
}

// ---------------------------------------------------------------------------
typedef CUresult (*PFN_encodeTiled)(
    CUtensorMap*, CUtensorMapDataType, cuuint32_t, void*,
    const cuuint64_t*, const cuuint64_t*, const cuuint32_t*, const cuuint32_t*,
    CUtensorMapInterleave, CUtensorMapSwizzle, CUtensorMapL2promotion,
    CUtensorMapFloatOOBfill);

extern "C" void kernel_launch(void* const* d_in, const int* in_sizes, int n_in,
                              void* d_out, int out_size)
{
    const float* x  = (const float*)d_in[0];
    const float* wq = (const float*)d_in[1];
    const float* wk = (const float*)d_in[2];
    const float* wv = (const float*)d_in[3];
    const float* wo = (const float*)d_in[4];
    float* out = (float*)d_out;

    uint32_t *px, *pwq, *pwk, *pwv, *pwo, *pq, *pk, *pv, *pao;
    cudaGetSymbolAddress((void**)&px,  g_x);
    cudaGetSymbolAddress((void**)&pwq, g_wq);
    cudaGetSymbolAddress((void**)&pwk, g_wk);
    cudaGetSymbolAddress((void**)&pwv, g_wv);
    cudaGetSymbolAddress((void**)&pwo, g_wo);
    cudaGetSymbolAddress((void**)&pq,  g_q);
    cudaGetSymbolAddress((void**)&pk,  g_k);
    cudaGetSymbolAddress((void**)&pv,  g_v);
    cudaGetSymbolAddress((void**)&pao, g_ao);

    // tensormaps via driver entry point (no -lcuda link needed)
    void* fnp = nullptr;
    cudaDriverEntryPointQueryResult qr;
    cudaGetDriverEntryPointByVersion("cuTensorMapEncodeTiled", &fnp, 12000,
                                     cudaEnableDefault, &qr);
    PFN_encodeTiled enc = (PFN_encodeTiled)fnp;

    CUtensorMap tX, tWq, tWk, tWv, tAO, tWO;
    auto mk = [&](CUtensorMap* m, void* base, cuuint64_t rows) {
        cuuint64_t dims[2]    = {DMODEL, rows};
        cuuint64_t strides[1] = {DMODEL * 4};
        cuuint32_t box[2]     = {32, 128};
        cuuint32_t es[2]      = {1, 1};
        enc(m, CU_TENSOR_MAP_DATA_TYPE_FLOAT32, 2, base, dims, strides, box, es,
            CU_TENSOR_MAP_INTERLEAVE_NONE, CU_TENSOR_MAP_SWIZZLE_128B,
            CU_TENSOR_MAP_L2_PROMOTION_L2_128B, CU_TENSOR_MAP_FLOAT_OOB_FILL_NONE);
    };
    mk(&tX,  px,  MROWS);
    mk(&tWq, pwq, DMODEL);
    mk(&tWk, pwk, DMODEL);
    mk(&tWv, pwv, DMODEL);
    mk(&tAO, pao, MROWS);
    mk(&tWO, pwo, DMODEL);

    cudaFuncSetAttribute(gemm_qkv_tma, cudaFuncAttributeMaxDynamicSharedMemorySize, TG_SMEM);
    cudaFuncSetAttribute(gemm_o_tma,   cudaFuncAttributeMaxDynamicSharedMemorySize, TG_SMEM);
    cudaFuncSetAttribute(attn_pipe_kernel, cudaFuncAttributeMaxDynamicSharedMemorySize,
                         ATT_SMEM_U32 * (int)sizeof(uint32_t));

    const int total4 = NX4 + 4 * NW4;
    cvt_all_kernel<<<total4 / 256, 256>>>(
        (const float4*)x, (const float4*)wq, (const float4*)wk,
        (const float4*)wv, (const float4*)wo,
        (uint4*)px, (uint4*)pwq, (uint4*)pwk, (uint4*)pwv, (uint4*)pwo);

    const dim3 qkv_grid(DMODEL / 128, MROWS / 128, 3);   // (8, 64, 3)
    gemm_qkv_tma<<<qkv_grid, 256, TG_SMEM>>>(tX, tWq, tWk, tWv, pq, pk, pv);

    const dim3 agrid(SEQ / 128, BATCH * NHEADS);         // (16, 64)
    attn_pipe_kernel<<<agrid, 256, ATT_SMEM_U32 * sizeof(uint32_t)>>>(pq, pk, pv, pao);

    const dim3 ogrid(DMODEL / 128, MROWS / 128);         // (8, 64)
    gemm_o_tma<<<ogrid, 256, TG_SMEM>>>(tAO, tWO, out);
}

// round 13
// speedup vs baseline: 2.2541x; 1.0453x over previous
#include <cuda_runtime.h>
#include <cuda.h>
#include <cuda_bf16.h>
#include <cstdint>

#define BATCH 4
#define SEQ 2048
#define DMODEL 1024
#define NHEADS 16
#define HDIM 64
#define MROWS (BATCH * SEQ)      // 8192

__device__ uint32_t g_x [MROWS * DMODEL];               // x, tf32 bits
__device__ uint32_t g_wq[DMODEL * DMODEL];
__device__ uint32_t g_wk[DMODEL * DMODEL];
__device__ uint32_t g_wv[DMODEL * DMODEL];
__device__ uint32_t g_wo[DMODEL * DMODEL];
__device__ uint32_t g_q [BATCH * NHEADS * SEQ * HDIM];  // [B,H,S,Dh] tf32 bits
__device__ uint32_t g_k [BATCH * NHEADS * SEQ * HDIM];  // [B,H,S,Dh]
__device__ uint32_t g_v [BATCH * NHEADS * HDIM * SEQ];  // [B,H,Dh,S]  (transposed)
__device__ uint32_t g_ao[BATCH * SEQ * DMODEL];         // [B,S,D] tf32 bits

__device__ __forceinline__ uint32_t f2tf32(float x) {
    uint32_t r;
    asm("cvt.rna.tf32.f32 %0, %1;" : "=r"(r) : "f"(x));
    return r;
}
__device__ __forceinline__ float fexp2(float x) {
    float y;
    asm("ex2.approx.ftz.f32 %0, %1;" : "=f"(y) : "f"(x));
    return y;
}
__device__ __forceinline__ void mma_tf32(float* c, const uint32_t* a, const uint32_t* b) {
    asm volatile(
        "mma.sync.aligned.m16n8k8.row.col.f32.tf32.tf32.f32 "
        "{%0,%1,%2,%3}, {%4,%5,%6,%7}, {%8,%9}, {%0,%1,%2,%3};"
        : "+f"(c[0]), "+f"(c[1]), "+f"(c[2]), "+f"(c[3])
        : "r"(a[0]), "r"(a[1]), "r"(a[2]), "r"(a[3]), "r"(b[0]), "r"(b[1]));
}
__device__ __forceinline__ void ldsm4(uint32_t& r0, uint32_t& r1,
                                      uint32_t& r2, uint32_t& r3, uint32_t addr) {
    asm volatile("ldmatrix.sync.aligned.m8n8.x4.shared.b16 {%0,%1,%2,%3}, [%4];"
                 : "=r"(r0), "=r"(r1), "=r"(r2), "=r"(r3) : "r"(addr));
}
__device__ __forceinline__ uint32_t smem_u32(const void* p) {
    return (uint32_t)__cvta_generic_to_shared(p);
}
// ---- TMA / mbarrier helpers ----
__device__ __forceinline__ void tma2d(uint32_t smem, const CUtensorMap* tmap,
                                      int x, int y, uint32_t mbar) {
    asm volatile(
        "cp.async.bulk.tensor.2d.shared::cta.global.tile.mbarrier::complete_tx::bytes "
        "[%0], [%1, {%2, %3}], [%4];"
        :: "r"(smem), "l"(tmap), "r"(x), "r"(y), "r"(mbar) : "memory");
}
__device__ __forceinline__ void tma3d(uint32_t smem, const CUtensorMap* tmap,
                                      int x, int y, int z, uint32_t mbar) {
    asm volatile(
        "cp.async.bulk.tensor.3d.shared::cta.global.tile.mbarrier::complete_tx::bytes "
        "[%0], [%1, {%2, %3, %4}], [%5];"
        :: "r"(smem), "l"(tmap), "r"(x), "r"(y), "r"(z), "r"(mbar) : "memory");
}
__device__ __forceinline__ void mbar_init(uint32_t mbar, uint32_t cnt) {
    asm volatile("mbarrier.init.shared.b64 [%0], %1;" :: "r"(mbar), "r"(cnt) : "memory");
}
__device__ __forceinline__ void mbar_expect_tx(uint32_t mbar, uint32_t bytes) {
    asm volatile("mbarrier.arrive.expect_tx.shared.b64 _, [%0], %1;"
                 :: "r"(mbar), "r"(bytes) : "memory");
}
__device__ __forceinline__ void mbar_arrive(uint32_t mbar) {
    asm volatile("mbarrier.arrive.shared.b64 _, [%0];" :: "r"(mbar) : "memory");
}
__device__ __forceinline__ void mbar_wait(uint32_t mbar, uint32_t phase) {
    uint32_t ok = 0;
    while (!ok) {
        asm volatile("{\n\t.reg .pred p;\n\t"
                     "mbarrier.try_wait.parity.acquire.cta.shared::cta.b64 p, [%1], %2;\n\t"
                     "selp.b32 %0, 1, 0, p;\n\t}"
                     : "=r"(ok) : "r"(mbar), "r"(phase) : "memory");
    }
}

// ---------------------------------------------------------------------------
// fp32 -> tf32-bits elementwise convert, single fused launch
// ---------------------------------------------------------------------------
#define NX4 (MROWS * DMODEL / 4)
#define NW4 (DMODEL * DMODEL / 4)
__global__ __launch_bounds__(256) void cvt_all_kernel(
    const float4* __restrict__ x,
    const float4* __restrict__ wq, const float4* __restrict__ wk,
    const float4* __restrict__ wv, const float4* __restrict__ wo,
    uint4* __restrict__ ox,
    uint4* __restrict__ oq, uint4* __restrict__ ok,
    uint4* __restrict__ ov, uint4* __restrict__ oo)
{
    const int i = blockIdx.x * blockDim.x + threadIdx.x;
    const float4* src;
    uint4* dst;
    int off;
    if (i < NX4) { src = x; dst = ox; off = i; }
    else {
        const int k = i - NX4;
        const int w = k >> 18;
        off = k & (NW4 - 1);
        src = (w == 0) ? wq : (w == 1) ? wk : (w == 2) ? wv : wo;
        dst = (w == 0) ? oq : (w == 1) ? ok : (w == 2) ? ov : oo;
    }
    float4 v = src[off];
    dst[off] = make_uint4(f2tf32(v.x), f2tf32(v.y), f2tf32(v.z), f2tf32(v.w));
}

// ---------------------------------------------------------------------------
// TMA-fed tf32 GEMM (unchanged from R10): 128x128 tile, BK=32, 3-stage.
// ---------------------------------------------------------------------------
#define STAGEB 16384
#define TG_SMEM (1024 + 6 * STAGEB)

struct GemmAcc { float a[4][4][4]; };

__device__ __forceinline__ void tma_gemm_core(
    const CUtensorMap* tA, const CUtensorMap* tB, int bm, int bn, GemmAcc& G)
{
    extern __shared__ uint32_t gsm[];
    const uint32_t sb  = smem_u32(gsm);
    const uint32_t stA = sb + 1024;
    const uint32_t stB = sb + 1024 + 3 * STAGEB;
    const int tid  = threadIdx.x;
    const int warp = tid >> 5;
    const int lane = tid & 31;
    const int wm = warp >> 2, wn = warp & 3;
    const int g  = lane >> 3, ri = lane & 7;

    if (tid == 0) {
#pragma unroll
        for (int s = 0; s < 3; s++) {
            mbar_init(sb + 64 + 16 * s, 1);
            mbar_init(sb + 160 + 16 * s, 256);
        }
    }
    __syncthreads();
    if (tid == 0) {
#pragma unroll
        for (int s = 0; s < 3; s++) {
            mbar_expect_tx(sb + 64 + 16 * s, 2 * STAGEB);
            tma2d(stA + s * STAGEB, tA, s * 32, bm, sb + 64 + 16 * s);
            tma2d(stB + s * STAGEB, tB, s * 32, bn, sb + 64 + 16 * s);
        }
    }

    uint32_t aRow[4], bRow[2];
#pragma unroll
    for (int mt = 0; mt < 4; mt++)
        aRow[mt] = (uint32_t)((wm * 64 + mt * 16 + (g & 1) * 8 + ri) * 128);
#pragma unroll
    for (int np = 0; np < 2; np++)
        bRow[np] = (uint32_t)((wn * 32 + np * 16 + (g >> 1) * 8 + ri) * 128);
    const int asel = g >> 1, bsel = g & 1;

#pragma unroll
    for (int i = 0; i < 4; i++)
#pragma unroll
        for (int j = 0; j < 4; j++)
#pragma unroll
            for (int q = 0; q < 4; q++) G.a[i][j][q] = 0.0f;

    for (int t = 0; t < 32; t++) {
        const int buf = t % 3;
        const uint32_t sA = stA + (uint32_t)buf * STAGEB;
        const uint32_t sBs = stB + (uint32_t)buf * STAGEB;
        mbar_wait(sb + 64 + 16 * buf, (uint32_t)((t / 3) & 1));

#pragma unroll
        for (int ks = 0; ks < 4; ks++) {
            const uint32_t aCh = (uint32_t)(((ks * 2 + asel) ^ ri) * 16);
            const uint32_t bCh = (uint32_t)(((ks * 2 + bsel) ^ ri) * 16);
            uint32_t af[4][4], bf[4][2];
#pragma unroll
            for (int mt = 0; mt < 4; mt++)
                ldsm4(af[mt][0], af[mt][1], af[mt][2], af[mt][3],
                      sA + aRow[mt] + aCh);
#pragma unroll
            for (int np = 0; np < 2; np++)
                ldsm4(bf[2 * np][0], bf[2 * np][1], bf[2 * np + 1][0], bf[2 * np + 1][1],
                      sBs + bRow[np] + bCh);
#pragma unroll
            for (int mt = 0; mt < 4; mt++)
#pragma unroll
                for (int nt = 0; nt < 4; nt++)
                    mma_tf32(G.a[mt][nt], af[mt], bf[nt]);
        }

        mbar_arrive(sb + 160 + 16 * buf);
        if (t + 3 < 32 && tid == 0) {
            mbar_wait(sb + 160 + 16 * buf, (uint32_t)((t / 3) & 1));
            mbar_expect_tx(sb + 64 + 16 * buf, 2 * STAGEB);
            tma2d(sA,  tA, (t + 3) * 32, bm, sb + 64 + 16 * buf);
            tma2d(sBs, tB, (t + 3) * 32, bn, sb + 64 + 16 * buf);
        }
    }
}

__global__ __launch_bounds__(256, 2) void gemm_qkv_tma(
    const __grid_constant__ CUtensorMap tX,
    const __grid_constant__ CUtensorMap tWq,
    const __grid_constant__ CUtensorMap tWk,
    const __grid_constant__ CUtensorMap tWv,
    uint32_t* __restrict__ Oq, uint32_t* __restrict__ Ok,
    uint32_t* __restrict__ Ov)
{
    const int zi = blockIdx.z;
    const CUtensorMap* tW = (zi == 0) ? &tWq : (zi == 1) ? &tWk : &tWv;
    uint32_t* C = (zi == 0) ? Oq : (zi == 1) ? Ok : Ov;

    const int bm = blockIdx.y << 7;
    const int bn = blockIdx.x << 7;
    GemmAcc G;
    tma_gemm_core(&tX, tW, bm, bn, G);

    const int lane = threadIdx.x & 31;
    const int warp = threadIdx.x >> 5;
    const int r = lane >> 2, c = lane & 3;
    const int wm = warp >> 2, wn = warp & 3;
#pragma unroll
    for (int mt = 0; mt < 4; mt++) {
        const int m0 = bm + wm * 64 + mt * 16 + r;
#pragma unroll
        for (int nt = 0; nt < 4; nt++) {
            const int n = bn + wn * 32 + nt * 8 + c * 2;
            const int h = n >> 6;
            const int dh = n & 63;
#pragma unroll
            for (int half = 0; half < 2; half++) {
                const int m = m0 + half * 8;
                const int b = m >> 11;
                const int s = m & (SEQ - 1);
                const uint32_t v0 = f2tf32(G.a[mt][nt][half * 2]);
                const uint32_t v1 = f2tf32(G.a[mt][nt][half * 2 + 1]);
                if (zi == 2) {
                    const int base = ((b * NHEADS + h) * HDIM + dh) * SEQ + s;
                    C[base] = v0;
                    C[base + SEQ] = v1;
                } else {
                    *(uint2*)&C[((b * NHEADS + h) * SEQ + s) * HDIM + dh] =
                        make_uint2(v0, v1);
                }
            }
        }
    }
}

__global__ __launch_bounds__(256, 2) void gemm_o_tma(
    const __grid_constant__ CUtensorMap tA,
    const __grid_constant__ CUtensorMap tW,
    float* __restrict__ C)
{
    const int bm = blockIdx.y << 7;
    const int bn = blockIdx.x << 7;
    GemmAcc G;
    tma_gemm_core(&tA, &tW, bm, bn, G);

    const int lane = threadIdx.x & 31;
    const int warp = threadIdx.x >> 5;
    const int r = lane >> 2, c = lane & 3;
    const int wm = warp >> 2, wn = warp & 3;
#pragma unroll
    for (int mt = 0; mt < 4; mt++) {
        const int m0 = bm + wm * 64 + mt * 16 + r;
#pragma unroll
        for (int nt = 0; nt < 4; nt++) {
            const int n = bn + wn * 32 + nt * 8 + c * 2;
#pragma unroll
            for (int half = 0; half < 2; half++) {
                const int m = m0 + half * 8;
                float2 v = make_float2(G.a[mt][nt][half * 2],
                                       G.a[mt][nt][half * 2 + 1]);
                *(float2*)&C[m * DMODEL + n] = v;
            }
        }
    }
}

// ---------------------------------------------------------------------------
// TMA-fed tf32 flash attention (causal). q-tile 128, kv-tile 64, double
// buffered. Stage = two 8KB SW128 sub-tiles per operand.
//   K sub-tiles: dh-halves  -> loads (0,k0) and (32,k0)
//   V sub-tiles: s-halves   -> loads (k0,0) and (k0+32,0)   [R11 bug fixed]
// ---------------------------------------------------------------------------
#define APS 68
#define AT_KOFF 1024
#define AT_VOFF (1024 + 2 * 16384)
#define AT_POFF (1024 + 4 * 16384)
#define AT_SMEM (AT_POFF + 128 * APS * 4)    // 101376 B
#define QSCALE (0.125f * 1.4426950408889634f)

__global__ __launch_bounds__(256, 2) void attn_tma_kernel(
    const __grid_constant__ CUtensorMap tK,
    const __grid_constant__ CUtensorMap tV,
    const uint32_t* __restrict__ Q, uint32_t* __restrict__ O)
{
    extern __shared__ uint32_t smu[];
    const uint32_t sb = smem_u32(smu);
    uint32_t* Pu = smu + AT_POFF / 4;

    const int tid  = threadIdx.x;
    const int warp = tid >> 5;
    const int lane = tid & 31;
    const int r = lane >> 2;
    const int c = lane & 3;
    const int g  = lane >> 3;
    const int ri = lane & 7;

    const int bh = blockIdx.y;
    const int QT = gridDim.x - 1 - blockIdx.x;    // longest first
    const int q0 = QT << 7;
    const uint32_t* Qb = Q + bh * (SEQ * HDIM);

    if (tid == 0) {
        mbar_init(sb + 64, 1);  mbar_init(sb + 80, 1);
        mbar_init(sb + 128, 256); mbar_init(sb + 144, 256);
    }
    __syncthreads();

    const int T = 2 * QT + 1;
    auto issue_kv = [&](int t) {   // tid 0 only
        const int buf = t & 1;
        const int k0 = t << 6;
        const uint32_t fullb = sb + 64 + 16 * buf;
        mbar_expect_tx(fullb, 32768);
        const uint32_t kst = sb + AT_KOFF + buf * 16384;
        const uint32_t vst = sb + AT_VOFF + buf * 16384;
        tma3d(kst,        &tK, 0,       k0, bh, fullb);  // K dh 0-31, s tile
        tma3d(kst + 8192, &tK, 32,      k0, bh, fullb);  // K dh 32-63
        tma3d(vst,        &tV, k0,      0,  bh, fullb);  // V s 0-31 half
        tma3d(vst + 8192, &tV, k0 + 32, 0,  bh, fullb);  // V s 32-63 half (FIX)
    };
    if (tid == 0) {
        issue_kv(0);
        issue_kv(1);
    }

    // ---- stage Q tile into Pu, build resident frags ----
    {
        const int qrow = tid >> 1;
        const int qcol = (tid & 1) << 5;
#pragma unroll
        for (int cc = 0; cc < 32; cc += 4)
            *(uint4*)&Pu[qrow * APS + qcol + cc] =
                *(const uint4*)&Qb[(q0 + qrow) * HDIM + qcol + cc];
    }
    __syncthreads();

    const int qr = warp * 16 + r;
    uint32_t qf[8][4];
#pragma unroll
    for (int ks = 0; ks < 8; ks++) {
        const int d = ks * 8 + c;
        qf[ks][0] = f2tf32(QSCALE * __uint_as_float(Pu[qr * APS + d]));
        qf[ks][1] = f2tf32(QSCALE * __uint_as_float(Pu[(qr + 8) * APS + d]));
        qf[ks][2] = f2tf32(QSCALE * __uint_as_float(Pu[qr * APS + d + 4]));
        qf[ks][3] = f2tf32(QSCALE * __uint_as_float(Pu[(qr + 8) * APS + d + 4]));
    }

    uint32_t nRow[4];
#pragma unroll
    for (int np = 0; np < 4; np++)
        nRow[np] = (uint32_t)((np * 16 + (g >> 1) * 8 + ri) * 128);
    const int bsel = g & 1;
    const int offP = ((g & 1) * 8 + ri) * APS + (g >> 1) * 4;
    const uint32_t puB = smem_u32(Pu);

    float oacc[8][4];
#pragma unroll
    for (int nt = 0; nt < 8; nt++)
#pragma unroll
        for (int j = 0; j < 4; j++) oacc[nt][j] = 0.0f;
    float mrun[2] = {-1e30f, -1e30f};
    float lrun[2] = {0.0f, 0.0f};

    for (int t = 0; t <= T; t++) {
        const int buf = t & 1;
        const uint32_t phase = (uint32_t)((t >> 1) & 1);
        mbar_wait(sb + 64 + 16 * buf, phase);

        const uint32_t ktB = sb + AT_KOFF + (uint32_t)buf * 16384;
        const uint32_t vtB = sb + AT_VOFF + (uint32_t)buf * 16384;

        // ---- scores (log2-scaled): S = Q K^T ----
        float sacc[8][4];
#pragma unroll
        for (int nt = 0; nt < 8; nt++)
#pragma unroll
            for (int j = 0; j < 4; j++) sacc[nt][j] = 0.0f;
#pragma unroll
        for (int ks = 0; ks < 8; ks++) {
            const uint32_t base = ktB + (uint32_t)((ks >> 2) * 8192);
            const uint32_t ch = (uint32_t)((((2 * ks + bsel) & 7) ^ ri) * 16);
            uint32_t kf[8][2];
#pragma unroll
            for (int np = 0; np < 4; np++)
                ldsm4(kf[2 * np][0], kf[2 * np][1],
                      kf[2 * np + 1][0], kf[2 * np + 1][1],
                      base + nRow[np] + ch);
#pragma unroll
            for (int nt = 0; nt < 8; nt++)
                mma_tf32(sacc[nt], qf[ks], kf[nt]);
        }

        // ---- causal mask (diagonal region only) ----
        if (t >= 2 * QT) {
            const int kbase = t << 6;
#pragma unroll
            for (int nt = 0; nt < 8; nt++)
#pragma unroll
                for (int j = 0; j < 4; j++) {
                    const int kg = kbase + nt * 8 + 2 * c + (j & 1);
                    const int qg = q0 + warp * 16 + r + (j >> 1) * 8;
                    if (kg > qg) sacc[nt][j] = -1e30f;
                }
        }

        // ---- online softmax (base 2, MUFU ex2) ----
#pragma unroll
        for (int hh = 0; hh < 2; hh++) {
            float tm = -1e30f;
#pragma unroll
            for (int nt = 0; nt < 8; nt++)
                tm = fmaxf(tm, fmaxf(sacc[nt][2 * hh], sacc[nt][2 * hh + 1]));
            tm = fmaxf(tm, __shfl_xor_sync(0xffffffffu, tm, 1));
            tm = fmaxf(tm, __shfl_xor_sync(0xffffffffu, tm, 2));
            const float mnew  = fmaxf(mrun[hh], tm);
            const float alpha = fexp2(mrun[hh] - mnew);
            float ls = 0.0f;
            const int prow = (warp * 16 + r + hh * 8) * APS;
#pragma unroll
            for (int nt = 0; nt < 8; nt++) {
                const float p0 = fexp2(sacc[nt][2 * hh] - mnew);
                const float p1 = fexp2(sacc[nt][2 * hh + 1] - mnew);
                ls += p0 + p1;
                uint2 pv = make_uint2(f2tf32(p0), f2tf32(p1));
                *(uint2*)&Pu[prow + nt * 8 + 2 * c] = pv;
            }
            ls += __shfl_xor_sync(0xffffffffu, ls, 1);
            ls += __shfl_xor_sync(0xffffffffu, ls, 2);
            lrun[hh] = lrun[hh] * alpha + ls;
            mrun[hh] = mnew;
#pragma unroll
            for (int nt = 0; nt < 8; nt++) {
                oacc[nt][2 * hh]     *= alpha;
                oacc[nt][2 * hh + 1] *= alpha;
            }
        }
        __syncwarp();   // P region is warp-local: order STS before LDSM

        // ---- O += P V ----
#pragma unroll
        for (int ks = 0; ks < 8; ks++) {
            const uint32_t base = vtB + (uint32_t)((ks >> 2) * 8192);
            const uint32_t ch = (uint32_t)((((2 * ks + bsel) & 7) ^ ri) * 16);
            uint32_t pf[4], vf[8][2];
            ldsm4(pf[0], pf[1], pf[2], pf[3],
                  puB + (uint32_t)(warp * 16 * APS + ks * 8 + offP) * 4u);
#pragma unroll
            for (int np = 0; np < 4; np++)
                ldsm4(vf[2 * np][0], vf[2 * np][1],
                      vf[2 * np + 1][0], vf[2 * np + 1][1],
                      base + nRow[np] + ch);
#pragma unroll
            for (int nt = 0; nt < 8; nt++)
                mma_tf32(oacc[nt], pf, vf[nt]);
        }

        mbar_arrive(sb + 128 + 16 * buf);
        if (tid == 0 && t + 2 <= T) {
            mbar_wait(sb + 128 + 16 * buf, phase);
            issue_kv(t + 2);
        }
    }

    // ---- epilogue ----
    const float rinv0 = 1.0f / lrun[0];
    const float rinv1 = 1.0f / lrun[1];
    const int b = bh >> 4, h = bh & 15;
    const int row0 = q0 + qr;
#pragma unroll
    for (int nt = 0; nt < 8; nt++) {
        const int dh = nt * 8 + 2 * c;
        uint2 v0 = make_uint2(f2tf32(oacc[nt][0] * rinv0), f2tf32(oacc[nt][1] * rinv0));
        uint2 v1 = make_uint2(f2tf32(oacc[nt][2] * rinv1), f2tf32(oacc[nt][3] * rinv1));
        *(uint2*)&O[(b * SEQ + row0) * DMODEL + h * HDIM + dh] = v0;
        *(uint2*)&O[(b * SEQ + row0 + 8) * DMODEL + h * HDIM + dh] = v1;
    }
}

// ---------------------------------------------------------------------------
typedef CUresult (*PFN_encodeTiled)(
    CUtensorMap*, CUtensorMapDataType, cuuint32_t, void*,
    const cuuint64_t*, const cuuint64_t*, const cuuint32_t*, const cuuint32_t*,
    CUtensorMapInterleave, CUtensorMapSwizzle, CUtensorMapL2promotion,
    CUtensorMapFloatOOBfill);

extern "C" void kernel_launch(void* const* d_in, const int* in_sizes, int n_in,
                              void* d_out, int out_size)
{
    const float* x  = (const float*)d_in[0];
    const float* wq = (const float*)d_in[1];
    const float* wk = (const float*)d_in[2];
    const float* wv = (const float*)d_in[3];
    const float* wo = (const float*)d_in[4];
    float* out = (float*)d_out;

    uint32_t *px, *pwq, *pwk, *pwv, *pwo, *pq, *pk, *pv, *pao;
    cudaGetSymbolAddress((void**)&px,  g_x);
    cudaGetSymbolAddress((void**)&pwq, g_wq);
    cudaGetSymbolAddress((void**)&pwk, g_wk);
    cudaGetSymbolAddress((void**)&pwv, g_wv);
    cudaGetSymbolAddress((void**)&pwo, g_wo);
    cudaGetSymbolAddress((void**)&pq,  g_q);
    cudaGetSymbolAddress((void**)&pk,  g_k);
    cudaGetSymbolAddress((void**)&pv,  g_v);
    cudaGetSymbolAddress((void**)&pao, g_ao);

    void* fnp = nullptr;
    cudaDriverEntryPointQueryResult qr;
    cudaGetDriverEntryPointByVersion("cuTensorMapEncodeTiled", &fnp, 12000,
                                     cudaEnableDefault, &qr);
    PFN_encodeTiled enc = (PFN_encodeTiled)fnp;

    CUtensorMap tX, tWq, tWk, tWv, tAO, tWO, tKm, tVm;
    auto mk2 = [&](CUtensorMap* m, void* base, cuuint64_t rows) {
        cuuint64_t dims[2]    = {DMODEL, rows};
        cuuint64_t strides[1] = {DMODEL * 4};
        cuuint32_t box[2]     = {32, 128};
        cuuint32_t es[2]      = {1, 1};
        enc(m, CU_TENSOR_MAP_DATA_TYPE_FLOAT32, 2, base, dims, strides, box, es,
            CU_TENSOR_MAP_INTERLEAVE_NONE, CU_TENSOR_MAP_SWIZZLE_128B,
            CU_TENSOR_MAP_L2_PROMOTION_L2_128B, CU_TENSOR_MAP_FLOAT_OOB_FILL_NONE);
    };
    mk2(&tX,  px,  MROWS);
    mk2(&tWq, pwq, DMODEL);
    mk2(&tWk, pwk, DMODEL);
    mk2(&tWv, pwv, DMODEL);
    mk2(&tAO, pao, MROWS);
    mk2(&tWO, pwo, DMODEL);
    {   // K: [BH][S][Dh], box (dh=32, s=64)
        cuuint64_t dims[3]    = {HDIM, SEQ, BATCH * NHEADS};
        cuuint64_t strides[2] = {HDIM * 4, (cuuint64_t)SEQ * HDIM * 4};
        cuuint32_t box[3]     = {32, 64, 1};
        cuuint32_t es[3]      = {1, 1, 1};
        enc(&tKm, CU_TENSOR_MAP_DATA_TYPE_FLOAT32, 3, pk, dims, strides, box, es,
            CU_TENSOR_MAP_INTERLEAVE_NONE, CU_TENSOR_MAP_SWIZZLE_128B,
            CU_TENSOR_MAP_L2_PROMOTION_L2_128B, CU_TENSOR_MAP_FLOAT_OOB_FILL_NONE);
    }
    {   // V: [BH][Dh][S], box (s=32, dh=64)
        cuuint64_t dims[3]    = {SEQ, HDIM, BATCH * NHEADS};
        cuuint64_t strides[2] = {SEQ * 4, (cuuint64_t)SEQ * HDIM * 4};
        cuuint32_t box[3]     = {32, 64, 1};
        cuuint32_t es[3]      = {1, 1, 1};
        enc(&tVm, CU_TENSOR_MAP_DATA_TYPE_FLOAT32, 3, pv, dims, strides, box, es,
            CU_TENSOR_MAP_INTERLEAVE_NONE, CU_TENSOR_MAP_SWIZZLE_128B,
            CU_TENSOR_MAP_L2_PROMOTION_L2_128B, CU_TENSOR_MAP_FLOAT_OOB_FILL_NONE);
    }

    cudaFuncSetAttribute(gemm_qkv_tma, cudaFuncAttributeMaxDynamicSharedMemorySize, TG_SMEM);
    cudaFuncSetAttribute(gemm_o_tma,   cudaFuncAttributeMaxDynamicSharedMemorySize, TG_SMEM);
    cudaFuncSetAttribute(attn_tma_kernel, cudaFuncAttributeMaxDynamicSharedMemorySize, AT_SMEM);

    const int total4 = NX4 + 4 * NW4;
    cvt_all_kernel<<<total4 / 256, 256>>>(
        (const float4*)x, (const float4*)wq, (const float4*)wk,
        (const float4*)wv, (const float4*)wo,
        (uint4*)px, (uint4*)pwq, (uint4*)pwk, (uint4*)pwv, (uint4*)pwo);

    const dim3 qkv_grid(DMODEL / 128, MROWS / 128, 3);   // (8, 64, 3)
    gemm_qkv_tma<<<qkv_grid, 256, TG_SMEM>>>(tX, tWq, tWk, tWv, pq, pk, pv);

    const dim3 agrid(SEQ / 128, BATCH * NHEADS);         // (16, 64)
    attn_tma_kernel<<<agrid, 256, AT_SMEM>>>(tKm, tVm, pq, pao);

    const dim3 ogrid(DMODEL / 128, MROWS / 128);         // (8, 64)
    gemm_o_tma<<<ogrid, 256, TG_SMEM>>>(tAO, tWO, out);
}